// round 12
// baseline (speedup 1.0000x reference)
#include <cuda_runtime.h>
#include <cuda_bf16.h>
#include <cuda_fp16.h>
#include <math.h>
#include <stdint.h>

#define S_LEN 4096
#define HID 4096
#define NH 32
#define NKV 8
#define DH 128
#define ATT_SCALE 0.08838834764831845f  // 1/sqrt(128)

// ---------------- scratch ----------------
__device__ float g_Q[S_LEN * NH * DH];
__device__ float g_K[S_LEN * NKV * DH];
__device__ float g_V[S_LEN * NKV * DH];
__device__ __nv_bfloat16 g_hsHi[S_LEN * HID];
__device__ __nv_bfloat16 g_hsLo[S_LEN * HID];
__device__ __half g_hs16h[S_LEN * HID];
__device__ __half g_hs16l[S_LEN * HID];
__device__ __nv_bfloat16 g_wqkTHi[(HID + NKV * DH) * HID];
__device__ __nv_bfloat16 g_wqkTLo[(HID + NKV * DH) * HID];
__device__ __half g_wvT16[(NKV * DH) * HID];
__device__ __half g_woT16[HID * HID];
__device__ __half g_at16h[S_LEN * NH * DH];
__device__ __half g_at16l[S_LEN * NH * DH];

// ================= helpers =================
__device__ __forceinline__ uint32_t smem_u32(const void* p) {
    uint32_t a;
    asm("{ .reg .u64 t; cvta.to.shared.u64 t, %1; cvt.u32.u64 %0, t; }" : "=r"(a) : "l"(p));
    return a;
}
__device__ __forceinline__ uint32_t swz(uint32_t o) { return o ^ ((o >> 3) & 0x70); }

__device__ __forceinline__ void ldsm_x4(uint32_t& r0, uint32_t& r1, uint32_t& r2, uint32_t& r3,
                                        uint32_t addr) {
    asm volatile("ldmatrix.sync.aligned.m8n8.x4.shared.b16 {%0, %1, %2, %3}, [%4];"
                 : "=r"(r0), "=r"(r1), "=r"(r2), "=r"(r3) : "r"(addr));
}

template <typename T> struct MmaOp;
template <> struct MmaOp<__nv_bfloat16> {
    static __device__ __forceinline__ void run(float* c, const uint32_t* a, uint32_t b0,
                                               uint32_t b1) {
        asm volatile(
            "mma.sync.aligned.m16n8k16.row.col.f32.bf16.bf16.f32 "
            "{%0, %1, %2, %3}, {%4, %5, %6, %7}, {%8, %9}, {%0, %1, %2, %3};"
            : "+f"(c[0]), "+f"(c[1]), "+f"(c[2]), "+f"(c[3])
            : "r"(a[0]), "r"(a[1]), "r"(a[2]), "r"(a[3]), "r"(b0), "r"(b1));
    }
};
template <> struct MmaOp<__half> {
    static __device__ __forceinline__ void run(float* c, const uint32_t* a, uint32_t b0,
                                               uint32_t b1) {
        asm volatile(
            "mma.sync.aligned.m16n8k16.row.col.f32.f16.f16.f32 "
            "{%0, %1, %2, %3}, {%4, %5, %6, %7}, {%8, %9}, {%0, %1, %2, %3};"
            : "+f"(c[0]), "+f"(c[1]), "+f"(c[2]), "+f"(c[3])
            : "r"(a[0]), "r"(a[1]), "r"(a[2]), "r"(a[3]), "r"(b0), "r"(b1));
    }
};

__device__ __forceinline__ void cp16(uint32_t dst, const void* src) {
    asm volatile("cp.async.cg.shared.global [%0], [%1], 16;" :: "r"(dst), "l"(src));
}
#define CP_COMMIT() asm volatile("cp.async.commit_group;" ::: "memory")
#define CP_WAIT1() asm volatile("cp.async.wait_group 1;" ::: "memory")

// packed f32x2
typedef unsigned long long ull;
__device__ __forceinline__ ull fma2(ull a, ull b, ull c) {
    ull d;
    asm("fma.rn.f32x2 %0, %1, %2, %3;" : "=l"(d) : "l"(a), "l"(b), "l"(c));
    return d;
}
__device__ __forceinline__ ull dup2(float a) {
    ull d;
    asm("mov.b64 %0, {%1, %1};" : "=l"(d) : "f"(a));
    return d;
}
__device__ __forceinline__ float lo2(ull a) {
    float x, y;
    asm("mov.b64 {%0, %1}, %2;" : "=f"(x), "=f"(y) : "l"(a));
    return x + y;
}
__device__ __forceinline__ float2 unp2(ull a) {
    float2 r;
    asm("mov.b64 {%0, %1}, %2;" : "=f"(r.x), "=f"(r.y) : "l"(a));
    return r;
}

// ================= conversion kernels =================
__global__ void split_all_kernel(const float* __restrict__ in,
                                 __nv_bfloat16* __restrict__ hi,
                                 __nv_bfloat16* __restrict__ lo,
                                 __half* __restrict__ h16,
                                 __half* __restrict__ l16) {
    int i = (blockIdx.x * 256 + threadIdx.x) * 4;
    float4 v = *(const float4*)&in[i];
    float f[4] = {v.x, v.y, v.z, v.w};
    union { __nv_bfloat16 b[4]; uint2 u; } H, L;
    union { __half b[4]; uint2 u; } H16, L16;
#pragma unroll
    for (int j = 0; j < 4; ++j) {
        __nv_bfloat16 h = __float2bfloat16(f[j]);
        H.b[j] = h;
        L.b[j] = __float2bfloat16(f[j] - __bfloat162float(h));
        __half p = __float2half_rn(f[j]);
        H16.b[j] = p;
        L16.b[j] = __float2half_rn(f[j] - __half2float(p));
    }
    *(uint2*)&hi[i] = H.u;
    *(uint2*)&lo[i] = L.u;
    *(uint2*)&h16[i] = H16.u;
    *(uint2*)&l16[i] = L16.u;
}

__global__ void transpose_split_kernel(const float* __restrict__ W,
                                       __nv_bfloat16* __restrict__ hi,
                                       __nv_bfloat16* __restrict__ lo,
                                       int rows, int cols) {
    __shared__ float t[32][33];
    int c0 = blockIdx.x * 32, r0 = blockIdx.y * 32;
    int tx = threadIdx.x, ty = threadIdx.y;
#pragma unroll
    for (int j = 0; j < 4; ++j) {
        int r = ty + j * 8;
        t[r][tx] = W[(size_t)(r0 + r) * cols + c0 + tx];
    }
    __syncthreads();
#pragma unroll
    for (int j = 0; j < 4; ++j) {
        int r = ty + j * 8;
        float v = t[tx][r];
        __nv_bfloat16 h = __float2bfloat16(v);
        size_t o = (size_t)(c0 + r) * rows + r0 + tx;
        hi[o] = h;
        lo[o] = __float2bfloat16(v - __bfloat162float(h));
    }
}

__global__ void transpose_f16_kernel(const float* __restrict__ W,
                                     __half* __restrict__ out, int rows, int cols) {
    __shared__ float t[32][33];
    int c0 = blockIdx.x * 32, r0 = blockIdx.y * 32;
    int tx = threadIdx.x, ty = threadIdx.y;
#pragma unroll
    for (int j = 0; j < 4; ++j) {
        int r = ty + j * 8;
        t[r][tx] = W[(size_t)(r0 + r) * cols + c0 + tx];
    }
    __syncthreads();
#pragma unroll
    for (int j = 0; j < 4; ++j) {
        int r = ty + j * 8;
        out[(size_t)(c0 + r) * rows + r0 + tx] = __float2half_rn(t[tx][r]);
    }
}

// ================= HMMA GEMM (R8 geometry, dual-output epilogue) =================
template <typename T, bool SPLIT_B>
__global__ __launch_bounds__(256, 2)
void gemm_tc(const T* __restrict__ Ahi, const T* __restrict__ Alo,
             const T* __restrict__ Bhi, const T* __restrict__ Blo,
             float* __restrict__ C0, float* __restrict__ C1,
             int N0, int N1, int K) {
    constexpr uint32_t B_OFF = 32768;
    constexpr uint32_t STG = B_OFF + (SPLIT_B ? 16384 : 8192);
    extern __shared__ char smem[];
    const uint32_t sb = smem_u32(smem);
    const int tid = threadIdx.x, lane = tid & 31, wid = tid >> 5;
    const int m0 = blockIdx.y * 128, n0 = blockIdx.x * 64;
    const int wm = (wid >> 1) * 32, wn = (wid & 1) * 32;

    const T* aptr[4];
    uint32_t asw[4];
#pragma unroll
    for (int i = 0; i < 4; ++i) {
        int idx = tid + (i << 8);
        int r = idx >> 3, c = idx & 7;
        aptr[i] = Ahi + (size_t)(m0 + r) * K + (c << 3);
        asw[i] = swz(r * 128 + c * 16);
    }
    const T* bptr[2];
    uint32_t bsw[2];
#pragma unroll
    for (int i = 0; i < 2; ++i) {
        int idx = tid + (i << 8);
        int r = idx >> 3, c = idx & 7;
        bptr[i] = Bhi + (size_t)(n0 + r) * K + (c << 3);
        bsw[i] = swz(r * 128 + c * 16);
    }
    const ptrdiff_t dA = Alo - Ahi;
    const ptrdiff_t dB = SPLIT_B ? (Blo - Bhi) : 0;

    float acc[2][4][4];
#pragma unroll
    for (int mt = 0; mt < 2; ++mt)
#pragma unroll
        for (int nt = 0; nt < 4; ++nt)
#pragma unroll
            for (int q = 0; q < 4; ++q) acc[mt][nt][q] = 0.f;

    const int NKT = K >> 6;
#pragma unroll
    for (int s = 0; s < 2; ++s) {
        const uint32_t st = sb + s * STG;
        const int ko = s * 64;
#pragma unroll
        for (int i = 0; i < 4; ++i) {
            cp16(st + asw[i], aptr[i] + ko);
            cp16(st + 16384 + asw[i], aptr[i] + dA + ko);
        }
#pragma unroll
        for (int i = 0; i < 2; ++i) {
            cp16(st + B_OFF + bsw[i], bptr[i] + ko);
            if (SPLIT_B) cp16(st + B_OFF + 8192 + bsw[i], bptr[i] + dB + ko);
        }
        CP_COMMIT();
    }

    const int row_off = ((lane >> 3) & 1) * 8 + (lane & 7);
    const int kxtra = (lane >> 4) * 16;
    const uint32_t a_lb = (uint32_t)((wm + row_off) * 128 + kxtra);
    const uint32_t b_lb = (uint32_t)((wn + row_off) * 128 + kxtra);

    for (int kt = 0; kt < NKT; ++kt) {
        CP_WAIT1();
        __syncthreads();
        const uint32_t st = sb + (uint32_t)(kt & 1) * STG;
#pragma unroll
        for (int ks = 0; ks < 4; ++ks) {
            uint32_t ah[2][4], al[2][4], bh[2][4];
#pragma unroll
            for (int mt = 0; mt < 2; ++mt) {
                uint32_t off = swz(a_lb + mt * 16 * 128 + ks * 32);
                ldsm_x4(ah[mt][0], ah[mt][1], ah[mt][2], ah[mt][3], st + off);
                ldsm_x4(al[mt][0], al[mt][1], al[mt][2], al[mt][3], st + 16384 + off);
            }
#pragma unroll
            for (int nt2 = 0; nt2 < 2; ++nt2)
                ldsm_x4(bh[nt2][0], bh[nt2][1], bh[nt2][2], bh[nt2][3],
                        st + B_OFF + swz(b_lb + nt2 * 16 * 128 + ks * 32));
            if (SPLIT_B) {
                uint32_t bl[2][4];
#pragma unroll
                for (int nt2 = 0; nt2 < 2; ++nt2)
                    ldsm_x4(bl[nt2][0], bl[nt2][1], bl[nt2][2], bl[nt2][3],
                            st + B_OFF + 8192 + swz(b_lb + nt2 * 16 * 128 + ks * 32));
#pragma unroll
                for (int mt = 0; mt < 2; ++mt)
#pragma unroll
                    for (int nt = 0; nt < 4; ++nt) {
                        MmaOp<T>::run(acc[mt][nt], ah[mt],
                                      bh[nt >> 1][nt & 1], bh[nt >> 1][2 + (nt & 1)]);
                        MmaOp<T>::run(acc[mt][nt], ah[mt],
                                      bl[nt >> 1][nt & 1], bl[nt >> 1][2 + (nt & 1)]);
                        MmaOp<T>::run(acc[mt][nt], al[mt],
                                      bh[nt >> 1][nt & 1], bh[nt >> 1][2 + (nt & 1)]);
                    }
            } else {
#pragma unroll
                for (int mt = 0; mt < 2; ++mt)
#pragma unroll
                    for (int nt = 0; nt < 4; ++nt) {
                        MmaOp<T>::run(acc[mt][nt], ah[mt],
                                      bh[nt >> 1][nt & 1], bh[nt >> 1][2 + (nt & 1)]);
                        MmaOp<T>::run(acc[mt][nt], al[mt],
                                      bh[nt >> 1][nt & 1], bh[nt >> 1][2 + (nt & 1)]);
                    }
            }
        }
        __syncthreads();
        if (kt + 2 < NKT) {
            const uint32_t st2 = sb + (uint32_t)(kt & 1) * STG;
            const int ko = (kt + 2) * 64;
#pragma unroll
            for (int i = 0; i < 4; ++i) {
                cp16(st2 + asw[i], aptr[i] + ko);
                cp16(st2 + 16384 + asw[i], aptr[i] + dA + ko);
            }
#pragma unroll
            for (int i = 0; i < 2; ++i) {
                cp16(st2 + B_OFF + bsw[i], bptr[i] + ko);
                if (SPLIT_B) cp16(st2 + B_OFF + 8192 + bsw[i], bptr[i] + dB + ko);
            }
        }
        CP_COMMIT();
    }

    float* Cc;
    int Nc, col0;
    if (n0 < N0) {
        Cc = C0; Nc = N0; col0 = n0;
    } else {
        Cc = C1; Nc = N1; col0 = n0 - N0;
    }
#pragma unroll
    for (int mt = 0; mt < 2; ++mt) {
        const int row = m0 + wm + mt * 16 + (lane >> 2);
#pragma unroll
        for (int nt = 0; nt < 4; ++nt) {
            const int col = col0 + wn + nt * 8 + (lane & 3) * 2;
            float* p0 = Cc + (size_t)row * Nc + col;
            *(float2*)p0 = make_float2(acc[mt][nt][0], acc[mt][nt][1]);
            *(float2*)(p0 + 8 * (size_t)Nc) = make_float2(acc[mt][nt][2], acc[mt][nt][3]);
        }
    }
}

// ---------------- RoPE ----------------
__global__ void rope_kernel(float* __restrict__ X, int nh) {
    const int s = blockIdx.x;
    const int d = threadIdx.x;
    const float e = (float)d * (1.0f / 64.0f);
    const float invf = 1.0f / powf(10000.0f, e);
    const float ang = (float)s * invf;
    float sn, cs;
    sincosf(ang, &sn, &cs);
    float* p = X + (size_t)s * nh * DH;
    for (int h = 0; h < nh; ++h) {
        const float x1 = p[d];
        const float x2 = p[d + 64];
        p[d] = x1 * cs - x2 * sn;
        p[d + 64] = x2 * cs + x1 * sn;
        p += DH;
    }
}

// ---------------- fused attention, 2 CTAs/SM (smem 116480 B) ----------------
// Buffers: sq 64x130 (Q, resident), skv 128x130 (K -> V -> lmK|lmV), sc 64x65.
#define QP2 130
#define KV2 130
#define SC2 65
__global__ __launch_bounds__(512, 2)
void fused_attn_kernel(const float* __restrict__ Q, const float* __restrict__ K,
                       const float* __restrict__ V,
                       __half* __restrict__ atHi, __half* __restrict__ atLo) {
    extern __shared__ float sm[];
    float* sq = sm;                   // 64 x 130
    float* skv = sq + 64 * QP2;       // 128 x 130
    float* sc = skv + 128 * KV2;      // 64 x 65

    const int tid = threadIdx.x;
    const int h = blockIdx.y;
    const int n = blockIdx.x;
    const int kvh = h >> 2;
    const int q0 = n * 64;
    const int key0 = q0 - 64;
    const int w = tid >> 5, lane = tid & 31;

    // ---- load Q + local K window (ull stores; rows are 8B- not 16B-aligned) ----
#pragma unroll
    for (int it = 0; it < 4; ++it) {
        int idx = tid + it * 512;
        int r = idx >> 5, c4 = idx & 31;
        float4 v4 = *(const float4*)&Q[(size_t)(q0 + r) * (NH * DH) + h * DH + c4 * 4];
        ull* d = (ull*)&sq[r * QP2 + c4 * 4];
        d[0] = *(ull*)&v4.x;
        d[1] = *(ull*)&v4.z;
    }
#pragma unroll
    for (int it = 0; it < 8; ++it) {
        int idx = tid + it * 512;
        int r = idx >> 5, c4 = idx & 31;
        int pos = key0 + r;
        float4 kv = make_float4(0.f, 0.f, 0.f, 0.f);
        if (pos >= 0)
            kv = *(const float4*)&K[(size_t)pos * (NKV * DH) + kvh * DH + c4 * 4];
        ull* d = (ull*)&skv[r * KV2 + c4 * 4];
        d[0] = *(ull*)&kv.x;
        d[1] = *(ull*)&kv.z;
    }
    __syncthreads();

    // ---- phase 1 scores ----
    {
        const int i = tid >> 3;
        const int jo = tid & 7;
        ull s2[8];
        ull s642 = 0;
#pragma unroll
        for (int m = 0; m < 8; ++m) s2[m] = 0;
        const float* qrow = sq + i * QP2;
        for (int d0 = 0; d0 < 128; d0 += 8) {
            ull q2[4];
            q2[0] = *(const ull*)&qrow[d0];
            q2[1] = *(const ull*)&qrow[d0 + 2];
            q2[2] = *(const ull*)&qrow[d0 + 4];
            q2[3] = *(const ull*)&qrow[d0 + 6];
#pragma unroll
            for (int m = 0; m < 8; ++m) {
                const ull* kr = (const ull*)(skv + (i + jo + 8 * m) * KV2 + d0);
#pragma unroll
                for (int dd = 0; dd < 4; ++dd) s2[m] = fma2(q2[dd], kr[dd], s2[m]);
            }
            if (jo == 0) {
                const ull* kr = (const ull*)(skv + (i + 64) * KV2 + d0);
#pragma unroll
                for (int dd = 0; dd < 4; ++dd) s642 = fma2(q2[dd], kr[dd], s642);
            }
        }
#pragma unroll
        for (int m = 0; m < 8; ++m) sc[i * SC2 + jo + 8 * m] = lo2(s2[m]) * ATT_SCALE;
        if (jo == 0) sc[i * SC2 + 64] = lo2(s642) * ATT_SCALE;
    }
    __syncthreads();  // scores done; K no longer needed

    // ---- overwrite skv with local V window; softmax in parallel (tid<64) ----
#pragma unroll
    for (int it = 0; it < 8; ++it) {
        int idx = tid + it * 512;
        int r = idx >> 5, c4 = idx & 31;
        int pos = key0 + r;
        float4 vv = make_float4(0.f, 0.f, 0.f, 0.f);
        if (pos >= 0)
            vv = *(const float4*)&V[(size_t)pos * (NKV * DH) + kvh * DH + c4 * 4];
        ull* d = (ull*)&skv[r * KV2 + c4 * 4];
        d[0] = *(ull*)&vv.x;
        d[1] = *(ull*)&vv.z;
    }
    if (tid < 64) {
        float* row = sc + tid * SC2;
        float mx = row[0];
        for (int j = 1; j < 65; ++j) mx = fmaxf(mx, row[j]);
        float sum = 0.f;
        for (int j = 0; j < 65; ++j) {
            float ex = expf(row[j] - mx);
            row[j] = ex;
            sum += ex;
        }
        float inv = 1.f / sum;
        for (int j = 0; j < 65; ++j) row[j] *= inv;
    }
    __syncthreads();

    // ---- phase 1 AV -> registers, 16 warps x 4 queries ----
    ull lo_[4][2];
#pragma unroll
    for (int iq = 0; iq < 4; ++iq) {
        const int i = w * 4 + iq;
        const float* wrow = sc + i * SC2;
        ull o0 = 0, o1 = 0;
#pragma unroll 5
        for (int jj = 0; jj < 65; ++jj) {
            ull wt2 = dup2(wrow[jj]);
            const ull* v2 = (const ull*)(skv + (i + jj) * KV2 + lane * 4);
            o0 = fma2(wt2, v2[0], o0);
            o1 = fma2(wt2, v2[1], o1);
        }
        lo_[iq][0] = o0;
        lo_[iq][1] = o1;
    }
    __syncthreads();  // phase-1 reads of skv/sc done

    // ---- phase 2: lmK rows 0-63, lmV rows 64-127 of skv ----
#pragma unroll
    for (int it = 0; it < 8; ++it) {
        int idx = tid + it * 512;
        int r = (idx >> 5) & 63;       // 0..63
        int which = idx >> 11;         // 0: K, 1: V (idx 0..2047 K, 2048..4095 V)
        int c4 = idx & 31;
        int pos = r * 64;
        const float* src = which ? V : K;
        float4 vv = *(const float4*)&src[(size_t)pos * (NKV * DH) + kvh * DH + c4 * 4];
        ull* d = (ull*)&skv[(which * 64 + r) * KV2 + c4 * 4];
        d[0] = *(ull*)&vv.x;
        d[1] = *(ull*)&vv.z;
    }
    __syncthreads();

    const int nvis = n + 1;
    // ---- phase 2 scores ----
    {
        const int i = tid >> 3;
        const int jo = tid & 7;
        ull s2[8];
#pragma unroll
        for (int m = 0; m < 8; ++m) s2[m] = 0;
        const float* qrow = sq + i * QP2;
        for (int d0 = 0; d0 < 128; d0 += 8) {
            ull q2[4];
            q2[0] = *(const ull*)&qrow[d0];
            q2[1] = *(const ull*)&qrow[d0 + 2];
            q2[2] = *(const ull*)&qrow[d0 + 4];
            q2[3] = *(const ull*)&qrow[d0 + 6];
#pragma unroll
            for (int m = 0; m < 8; ++m) {
                const ull* kr = (const ull*)(skv + (jo + 8 * m) * KV2 + d0);
#pragma unroll
                for (int dd = 0; dd < 4; ++dd) s2[m] = fma2(q2[dd], kr[dd], s2[m]);
            }
        }
#pragma unroll
        for (int m = 0; m < 8; ++m) {
            int jj = jo + 8 * m;
            if (jj < nvis) sc[i * SC2 + jj] = lo2(s2[m]) * ATT_SCALE;
        }
    }
    __syncthreads();

    if (tid < 64) {
        float* row = sc + tid * SC2;
        float mx = row[0];
        for (int j = 1; j < nvis; ++j) mx = fmaxf(mx, row[j]);
        float sum = 0.f;
        for (int j = 0; j < nvis; ++j) {
            float ex = expf(row[j] - mx);
            row[j] = ex;
            sum += ex;
        }
        float inv = 1.f / sum;
        for (int j = 0; j < nvis; ++j) row[j] *= inv;
    }
    __syncthreads();

    // ---- phase 2 AV + combine + store fp16 hi/lo ----
#pragma unroll
    for (int iq = 0; iq < 4; ++iq) {
        const int i = w * 4 + iq;
        const float* wrow = sc + i * SC2;
        ull o0 = 0, o1 = 0;
        for (int jj = 0; jj < nvis; ++jj) {
            ull wt2 = dup2(wrow[jj]);
            const ull* v2 = (const ull*)(skv + (64 + jj) * KV2 + lane * 4);
            o0 = fma2(wt2, v2[0], o0);
            o1 = fma2(wt2, v2[1], o1);
        }
        float2 ga = unp2(o0), gb = unp2(o1);
        float2 la = unp2(lo_[iq][0]), lb = unp2(lo_[iq][1]);
        float s4[4] = {0.7f * la.x + 0.3f * ga.x, 0.7f * la.y + 0.3f * ga.y,
                       0.7f * lb.x + 0.3f * gb.x, 0.7f * lb.y + 0.3f * gb.y};
        size_t idx = (size_t)(q0 + i) * (NH * DH) + h * DH + lane * 4;
        union { __half b2[4]; uint2 u; } H, L;
#pragma unroll
        for (int q = 0; q < 4; ++q) {
            __half hb = __float2half_rn(s4[q]);
            H.b2[q] = hb;
            L.b2[q] = __float2half_rn(s4[q] - __half2float(hb));
        }
        *(uint2*)&atHi[idx] = H.u;
        *(uint2*)&atLo[idx] = L.u;
    }
}

// ---------------- launch ----------------
extern "C" void kernel_launch(void* const* d_in, const int* in_sizes, int n_in,
                              void* d_out, int out_size) {
    const float* hs = (const float*)d_in[0];
    const float* wq = (const float*)d_in[1];
    const float* wk = (const float*)d_in[2];
    const float* wv = (const float*)d_in[3];
    const float* wo = (const float*)d_in[4];
    float* out = (float*)d_out;

    float *Q, *K, *V;
    __nv_bfloat16 *hsHi, *hsLo, *wqkTHi, *wqkTLo;
    __half *hs16h, *hs16l, *wvT16, *woT16, *at16h, *at16l;
    cudaGetSymbolAddress((void**)&Q, g_Q);
    cudaGetSymbolAddress((void**)&K, g_K);
    cudaGetSymbolAddress((void**)&V, g_V);
    cudaGetSymbolAddress((void**)&hsHi, g_hsHi);
    cudaGetSymbolAddress((void**)&hsLo, g_hsLo);
    cudaGetSymbolAddress((void**)&hs16h, g_hs16h);
    cudaGetSymbolAddress((void**)&hs16l, g_hs16l);
    cudaGetSymbolAddress((void**)&wqkTHi, g_wqkTHi);
    cudaGetSymbolAddress((void**)&wqkTLo, g_wqkTLo);
    cudaGetSymbolAddress((void**)&wvT16, g_wvT16);
    cudaGetSymbolAddress((void**)&woT16, g_woT16);
    cudaGetSymbolAddress((void**)&at16h, g_at16h);
    cudaGetSymbolAddress((void**)&at16l, g_at16l);

    const int SMEM_ATT = (64 * QP2 + 128 * KV2 + 64 * SC2) * 4;  // 116480
    const int SMEM_G3 = 2 * (32768 + 16384);
    const int SMEM_G2 = 2 * (32768 + 8192);
    cudaFuncSetAttribute(fused_attn_kernel, cudaFuncAttributeMaxDynamicSharedMemorySize, SMEM_ATT);
    cudaFuncSetAttribute(gemm_tc<__nv_bfloat16, true>,
                         cudaFuncAttributeMaxDynamicSharedMemorySize, SMEM_G3);
    cudaFuncSetAttribute(gemm_tc<__half, false>,
                         cudaFuncAttributeMaxDynamicSharedMemorySize, SMEM_G2);

    // conversions feeding QK gemm
    split_all_kernel<<<(S_LEN * HID) / 1024, 256>>>(hs, hsHi, hsLo, hs16h, hs16l);
    transpose_split_kernel<<<dim3(HID / 32, HID / 32), dim3(32, 8)>>>(
        wq, wqkTHi, wqkTLo, HID, HID);
    transpose_split_kernel<<<dim3((NKV * DH) / 32, HID / 32), dim3(32, 8)>>>(
        wk, wqkTHi + (size_t)HID * HID, wqkTLo + (size_t)HID * HID, HID, NKV * DH);

    // fused Q+K gemm (ncu capture slot 4)
    gemm_tc<__nv_bfloat16, true><<<dim3((HID + NKV * DH) / 64, S_LEN / 128), 256, SMEM_G3>>>(
        hsHi, hsLo, wqkTHi, wqkTLo, Q, K, NH * DH, NKV * DH, HID);

    transpose_f16_kernel<<<dim3((NKV * DH) / 32, HID / 32), dim3(32, 8)>>>(wv, wvT16, HID, NKV * DH);
    gemm_tc<__half, false><<<dim3((NKV * DH) / 64, S_LEN / 128), 256, SMEM_G2>>>(
        hs16h, hs16l, wvT16, (const __half*)nullptr, V, V, NKV * DH, 0, HID);

    transpose_f16_kernel<<<dim3(HID / 32, HID / 32), dim3(32, 8)>>>(wo, woT16, HID, HID);

    rope_kernel<<<S_LEN, 64>>>(Q, NH);
    rope_kernel<<<S_LEN, 64>>>(K, NKV);

    fused_attn_kernel<<<dim3(S_LEN / 64, NH), 512, SMEM_ATT>>>(Q, K, V, at16h, at16l);

    gemm_tc<__half, false><<<dim3(HID / 64, S_LEN / 128), 256, SMEM_G2>>>(
        at16h, at16l, woT16, (const __half*)nullptr, out, out, HID, 0, HID);
}

// round 13
// speedup vs baseline: 1.1044x; 1.1044x over previous
#include <cuda_runtime.h>
#include <cuda_bf16.h>
#include <cuda_fp16.h>
#include <math.h>
#include <stdint.h>

#define S_LEN 4096
#define HID 4096
#define NH 32
#define NKV 8
#define DH 128
#define ATT_SCALE 0.08838834764831845f  // 1/sqrt(128)

// ---------------- scratch ----------------
__device__ float g_Q[S_LEN * NH * DH];
__device__ float g_K[S_LEN * NKV * DH];
__device__ float g_V[S_LEN * NKV * DH];
__device__ __nv_bfloat16 g_hsHi[S_LEN * HID];
__device__ __nv_bfloat16 g_hsLo[S_LEN * HID];
__device__ __half g_hs16h[S_LEN * HID];
__device__ __half g_hs16l[S_LEN * HID];
__device__ __nv_bfloat16 g_wqkTHi[(HID + NKV * DH) * HID];
__device__ __nv_bfloat16 g_wqkTLo[(HID + NKV * DH) * HID];
__device__ __half g_wvT16[(NKV * DH) * HID];
__device__ __half g_woT16[HID * HID];
__device__ __half g_at16h[S_LEN * NH * DH];
__device__ __half g_at16l[S_LEN * NH * DH];

// ================= helpers =================
__device__ __forceinline__ uint32_t smem_u32(const void* p) {
    uint32_t a;
    asm("{ .reg .u64 t; cvta.to.shared.u64 t, %1; cvt.u32.u64 %0, t; }" : "=r"(a) : "l"(p));
    return a;
}
__device__ __forceinline__ uint32_t swz(uint32_t o) { return o ^ ((o >> 3) & 0x70); }

__device__ __forceinline__ void ldsm_x4(uint32_t& r0, uint32_t& r1, uint32_t& r2, uint32_t& r3,
                                        uint32_t addr) {
    asm volatile("ldmatrix.sync.aligned.m8n8.x4.shared.b16 {%0, %1, %2, %3}, [%4];"
                 : "=r"(r0), "=r"(r1), "=r"(r2), "=r"(r3) : "r"(addr));
}

template <typename T> struct MmaOp;
template <> struct MmaOp<__nv_bfloat16> {
    static __device__ __forceinline__ void run(float* c, const uint32_t* a, uint32_t b0,
                                               uint32_t b1) {
        asm volatile(
            "mma.sync.aligned.m16n8k16.row.col.f32.bf16.bf16.f32 "
            "{%0, %1, %2, %3}, {%4, %5, %6, %7}, {%8, %9}, {%0, %1, %2, %3};"
            : "+f"(c[0]), "+f"(c[1]), "+f"(c[2]), "+f"(c[3])
            : "r"(a[0]), "r"(a[1]), "r"(a[2]), "r"(a[3]), "r"(b0), "r"(b1));
    }
};
template <> struct MmaOp<__half> {
    static __device__ __forceinline__ void run(float* c, const uint32_t* a, uint32_t b0,
                                               uint32_t b1) {
        asm volatile(
            "mma.sync.aligned.m16n8k16.row.col.f32.f16.f16.f32 "
            "{%0, %1, %2, %3}, {%4, %5, %6, %7}, {%8, %9}, {%0, %1, %2, %3};"
            : "+f"(c[0]), "+f"(c[1]), "+f"(c[2]), "+f"(c[3])
            : "r"(a[0]), "r"(a[1]), "r"(a[2]), "r"(a[3]), "r"(b0), "r"(b1));
    }
};

__device__ __forceinline__ void cp16(uint32_t dst, const void* src) {
    asm volatile("cp.async.cg.shared.global [%0], [%1], 16;" :: "r"(dst), "l"(src));
}
#define CP_COMMIT() asm volatile("cp.async.commit_group;" ::: "memory")
#define CP_WAIT1() asm volatile("cp.async.wait_group 1;" ::: "memory")

// packed f32x2
typedef unsigned long long ull;
__device__ __forceinline__ ull fma2(ull a, ull b, ull c) {
    ull d;
    asm("fma.rn.f32x2 %0, %1, %2, %3;" : "=l"(d) : "l"(a), "l"(b), "l"(c));
    return d;
}
__device__ __forceinline__ ull dup2(float a) {
    ull d;
    asm("mov.b64 %0, {%1, %1};" : "=l"(d) : "f"(a));
    return d;
}
__device__ __forceinline__ float lo2(ull a) {
    float x, y;
    asm("mov.b64 {%0, %1}, %2;" : "=f"(x), "=f"(y) : "l"(a));
    return x + y;
}
__device__ __forceinline__ float2 unp2(ull a) {
    float2 r;
    asm("mov.b64 {%0, %1}, %2;" : "=f"(r.x), "=f"(r.y) : "l"(a));
    return r;
}

// ================= conversion kernels =================
__global__ void split_all_kernel(const float* __restrict__ in,
                                 __nv_bfloat16* __restrict__ hi,
                                 __nv_bfloat16* __restrict__ lo,
                                 __half* __restrict__ h16,
                                 __half* __restrict__ l16) {
    int i = (blockIdx.x * 256 + threadIdx.x) * 4;
    float4 v = *(const float4*)&in[i];
    float f[4] = {v.x, v.y, v.z, v.w};
    union { __nv_bfloat16 b[4]; uint2 u; } H, L;
    union { __half b[4]; uint2 u; } H16, L16;
#pragma unroll
    for (int j = 0; j < 4; ++j) {
        __nv_bfloat16 h = __float2bfloat16(f[j]);
        H.b[j] = h;
        L.b[j] = __float2bfloat16(f[j] - __bfloat162float(h));
        __half p = __float2half_rn(f[j]);
        H16.b[j] = p;
        L16.b[j] = __float2half_rn(f[j] - __half2float(p));
    }
    *(uint2*)&hi[i] = H.u;
    *(uint2*)&lo[i] = L.u;
    *(uint2*)&h16[i] = H16.u;
    *(uint2*)&l16[i] = L16.u;
}

__global__ void transpose_split_kernel(const float* __restrict__ W,
                                       __nv_bfloat16* __restrict__ hi,
                                       __nv_bfloat16* __restrict__ lo,
                                       int rows, int cols) {
    __shared__ float t[32][33];
    int c0 = blockIdx.x * 32, r0 = blockIdx.y * 32;
    int tx = threadIdx.x, ty = threadIdx.y;
#pragma unroll
    for (int j = 0; j < 4; ++j) {
        int r = ty + j * 8;
        t[r][tx] = W[(size_t)(r0 + r) * cols + c0 + tx];
    }
    __syncthreads();
#pragma unroll
    for (int j = 0; j < 4; ++j) {
        int r = ty + j * 8;
        float v = t[tx][r];
        __nv_bfloat16 h = __float2bfloat16(v);
        size_t o = (size_t)(c0 + r) * rows + r0 + tx;
        hi[o] = h;
        lo[o] = __float2bfloat16(v - __bfloat162float(h));
    }
}

__global__ void transpose_f16_kernel(const float* __restrict__ W,
                                     __half* __restrict__ out, int rows, int cols) {
    __shared__ float t[32][33];
    int c0 = blockIdx.x * 32, r0 = blockIdx.y * 32;
    int tx = threadIdx.x, ty = threadIdx.y;
#pragma unroll
    for (int j = 0; j < 4; ++j) {
        int r = ty + j * 8;
        t[r][tx] = W[(size_t)(r0 + r) * cols + c0 + tx];
    }
    __syncthreads();
#pragma unroll
    for (int j = 0; j < 4; ++j) {
        int r = ty + j * 8;
        out[(size_t)(c0 + r) * rows + r0 + tx] = __float2half_rn(t[tx][r]);
    }
}

// ================= HMMA GEMM (R8 geometry, dual-output epilogue) =================
template <typename T, bool SPLIT_B>
__global__ __launch_bounds__(256, 2)
void gemm_tc(const T* __restrict__ Ahi, const T* __restrict__ Alo,
             const T* __restrict__ Bhi, const T* __restrict__ Blo,
             float* __restrict__ C0, float* __restrict__ C1,
             int N0, int N1, int K) {
    constexpr uint32_t B_OFF = 32768;
    constexpr uint32_t STG = B_OFF + (SPLIT_B ? 16384 : 8192);
    extern __shared__ char smem[];
    const uint32_t sb = smem_u32(smem);
    const int tid = threadIdx.x, lane = tid & 31, wid = tid >> 5;
    const int m0 = blockIdx.y * 128, n0 = blockIdx.x * 64;
    const int wm = (wid >> 1) * 32, wn = (wid & 1) * 32;

    const T* aptr[4];
    uint32_t asw[4];
#pragma unroll
    for (int i = 0; i < 4; ++i) {
        int idx = tid + (i << 8);
        int r = idx >> 3, c = idx & 7;
        aptr[i] = Ahi + (size_t)(m0 + r) * K + (c << 3);
        asw[i] = swz(r * 128 + c * 16);
    }
    const T* bptr[2];
    uint32_t bsw[2];
#pragma unroll
    for (int i = 0; i < 2; ++i) {
        int idx = tid + (i << 8);
        int r = idx >> 3, c = idx & 7;
        bptr[i] = Bhi + (size_t)(n0 + r) * K + (c << 3);
        bsw[i] = swz(r * 128 + c * 16);
    }
    const ptrdiff_t dA = Alo - Ahi;
    const ptrdiff_t dB = SPLIT_B ? (Blo - Bhi) : 0;

    float acc[2][4][4];
#pragma unroll
    for (int mt = 0; mt < 2; ++mt)
#pragma unroll
        for (int nt = 0; nt < 4; ++nt)
#pragma unroll
            for (int q = 0; q < 4; ++q) acc[mt][nt][q] = 0.f;

    const int NKT = K >> 6;
#pragma unroll
    for (int s = 0; s < 2; ++s) {
        const uint32_t st = sb + s * STG;
        const int ko = s * 64;
#pragma unroll
        for (int i = 0; i < 4; ++i) {
            cp16(st + asw[i], aptr[i] + ko);
            cp16(st + 16384 + asw[i], aptr[i] + dA + ko);
        }
#pragma unroll
        for (int i = 0; i < 2; ++i) {
            cp16(st + B_OFF + bsw[i], bptr[i] + ko);
            if (SPLIT_B) cp16(st + B_OFF + 8192 + bsw[i], bptr[i] + dB + ko);
        }
        CP_COMMIT();
    }

    const int row_off = ((lane >> 3) & 1) * 8 + (lane & 7);
    const int kxtra = (lane >> 4) * 16;
    const uint32_t a_lb = (uint32_t)((wm + row_off) * 128 + kxtra);
    const uint32_t b_lb = (uint32_t)((wn + row_off) * 128 + kxtra);

    for (int kt = 0; kt < NKT; ++kt) {
        CP_WAIT1();
        __syncthreads();
        const uint32_t st = sb + (uint32_t)(kt & 1) * STG;
#pragma unroll
        for (int ks = 0; ks < 4; ++ks) {
            uint32_t ah[2][4], al[2][4], bh[2][4];
#pragma unroll
            for (int mt = 0; mt < 2; ++mt) {
                uint32_t off = swz(a_lb + mt * 16 * 128 + ks * 32);
                ldsm_x4(ah[mt][0], ah[mt][1], ah[mt][2], ah[mt][3], st + off);
                ldsm_x4(al[mt][0], al[mt][1], al[mt][2], al[mt][3], st + 16384 + off);
            }
#pragma unroll
            for (int nt2 = 0; nt2 < 2; ++nt2)
                ldsm_x4(bh[nt2][0], bh[nt2][1], bh[nt2][2], bh[nt2][3],
                        st + B_OFF + swz(b_lb + nt2 * 16 * 128 + ks * 32));
            if (SPLIT_B) {
                uint32_t bl[2][4];
#pragma unroll
                for (int nt2 = 0; nt2 < 2; ++nt2)
                    ldsm_x4(bl[nt2][0], bl[nt2][1], bl[nt2][2], bl[nt2][3],
                            st + B_OFF + 8192 + swz(b_lb + nt2 * 16 * 128 + ks * 32));
#pragma unroll
                for (int mt = 0; mt < 2; ++mt)
#pragma unroll
                    for (int nt = 0; nt < 4; ++nt) {
                        MmaOp<T>::run(acc[mt][nt], ah[mt],
                                      bh[nt >> 1][nt & 1], bh[nt >> 1][2 + (nt & 1)]);
                        MmaOp<T>::run(acc[mt][nt], ah[mt],
                                      bl[nt >> 1][nt & 1], bl[nt >> 1][2 + (nt & 1)]);
                        MmaOp<T>::run(acc[mt][nt], al[mt],
                                      bh[nt >> 1][nt & 1], bh[nt >> 1][2 + (nt & 1)]);
                    }
            } else {
#pragma unroll
                for (int mt = 0; mt < 2; ++mt)
#pragma unroll
                    for (int nt = 0; nt < 4; ++nt) {
                        MmaOp<T>::run(acc[mt][nt], ah[mt],
                                      bh[nt >> 1][nt & 1], bh[nt >> 1][2 + (nt & 1)]);
                        MmaOp<T>::run(acc[mt][nt], al[mt],
                                      bh[nt >> 1][nt & 1], bh[nt >> 1][2 + (nt & 1)]);
                    }
            }
        }
        __syncthreads();
        if (kt + 2 < NKT) {
            const uint32_t st2 = sb + (uint32_t)(kt & 1) * STG;
            const int ko = (kt + 2) * 64;
#pragma unroll
            for (int i = 0; i < 4; ++i) {
                cp16(st2 + asw[i], aptr[i] + ko);
                cp16(st2 + 16384 + asw[i], aptr[i] + dA + ko);
            }
#pragma unroll
            for (int i = 0; i < 2; ++i) {
                cp16(st2 + B_OFF + bsw[i], bptr[i] + ko);
                if (SPLIT_B) cp16(st2 + B_OFF + 8192 + bsw[i], bptr[i] + dB + ko);
            }
        }
        CP_COMMIT();
    }

    float* Cc;
    int Nc, col0;
    if (n0 < N0) {
        Cc = C0; Nc = N0; col0 = n0;
    } else {
        Cc = C1; Nc = N1; col0 = n0 - N0;
    }
#pragma unroll
    for (int mt = 0; mt < 2; ++mt) {
        const int row = m0 + wm + mt * 16 + (lane >> 2);
#pragma unroll
        for (int nt = 0; nt < 4; ++nt) {
            const int col = col0 + wn + nt * 8 + (lane & 3) * 2;
            float* p0 = Cc + (size_t)row * Nc + col;
            *(float2*)p0 = make_float2(acc[mt][nt][0], acc[mt][nt][1]);
            *(float2*)(p0 + 8 * (size_t)Nc) = make_float2(acc[mt][nt][2], acc[mt][nt][3]);
        }
    }
}

// ---------------- RoPE ----------------
__global__ void rope_kernel(float* __restrict__ X, int nh) {
    const int s = blockIdx.x;
    const int d = threadIdx.x;
    const float e = (float)d * (1.0f / 64.0f);
    const float invf = 1.0f / powf(10000.0f, e);
    const float ang = (float)s * invf;
    float sn, cs;
    sincosf(ang, &sn, &cs);
    float* p = X + (size_t)s * nh * DH;
    for (int h = 0; h < nh; ++h) {
        const float x1 = p[d];
        const float x2 = p[d + 64];
        p[d] = x1 * cs - x2 * sn;
        p[d + 64] = x2 * cs + x1 * sn;
        p += DH;
    }
}

// ---------------- fused attention (R11 layout + row-union AV) ----------------
#define QP 132
#define KP 132
__global__ __launch_bounds__(512, 1)
void fused_attn_kernel(const float* __restrict__ Q, const float* __restrict__ K,
                       const float* __restrict__ V,
                       __half* __restrict__ atHi, __half* __restrict__ atLo) {
    extern __shared__ float sm[];
    float* sq = sm;                 // 64 x 132
    float* sk = sq + 64 * QP;       // 128 x 132 (phase2: landmark K)
    float* sv = sk + 128 * KP;      // 128 x 128 (phase2: landmark V)
    float* sc = sv + 128 * 128;     // 64 x 66

    const int tid = threadIdx.x;
    const int h = blockIdx.y;
    const int n = blockIdx.x;
    const int kvh = h >> 2;
    const int q0 = n * 64;
    const int key0 = q0 - 64;
    const int w = tid >> 5, lane = tid & 31;

#pragma unroll
    for (int it = 0; it < 4; ++it) {
        int idx = tid + it * 512;
        int r = idx >> 5, c4 = idx & 31;
        float4 v4 = *(const float4*)&Q[(size_t)(q0 + r) * (NH * DH) + h * DH + c4 * 4];
        *(float4*)&sq[r * QP + c4 * 4] = v4;
    }
#pragma unroll
    for (int it = 0; it < 8; ++it) {
        int idx = tid + it * 512;
        int r = idx >> 5, c4 = idx & 31;
        int pos = key0 + r;
        float4 kv = make_float4(0.f, 0.f, 0.f, 0.f);
        float4 vv = make_float4(0.f, 0.f, 0.f, 0.f);
        if (pos >= 0) {
            kv = *(const float4*)&K[(size_t)pos * (NKV * DH) + kvh * DH + c4 * 4];
            vv = *(const float4*)&V[(size_t)pos * (NKV * DH) + kvh * DH + c4 * 4];
        }
        *(float4*)&sk[r * KP + c4 * 4] = kv;
        *(float4*)&sv[r * 128 + c4 * 4] = vv;
    }
    __syncthreads();

    // ---- phase 1 scores ----
    {
        const int i = tid >> 3;
        const int jo = tid & 7;
        ull s2[8];
        ull s642 = 0;
#pragma unroll
        for (int m = 0; m < 8; ++m) s2[m] = 0;
        const float* qrow = sq + i * QP;
        for (int d0 = 0; d0 < 128; d0 += 8) {
            ull q2[4];
            q2[0] = *(const ull*)&qrow[d0];
            q2[1] = *(const ull*)&qrow[d0 + 2];
            q2[2] = *(const ull*)&qrow[d0 + 4];
            q2[3] = *(const ull*)&qrow[d0 + 6];
#pragma unroll
            for (int m = 0; m < 8; ++m) {
                const ull* kr = (const ull*)(sk + (i + jo + 8 * m) * KP + d0);
#pragma unroll
                for (int dd = 0; dd < 4; ++dd) s2[m] = fma2(q2[dd], kr[dd], s2[m]);
            }
            if (jo == 0) {
                const ull* kr = (const ull*)(sk + (i + 64) * KP + d0);
#pragma unroll
                for (int dd = 0; dd < 4; ++dd) s642 = fma2(q2[dd], kr[dd], s642);
            }
        }
#pragma unroll
        for (int m = 0; m < 8; ++m) sc[i * 66 + jo + 8 * m] = lo2(s2[m]) * ATT_SCALE;
        if (jo == 0) sc[i * 66 + 64] = lo2(s642) * ATT_SCALE;
    }
    __syncthreads();

    if (tid < 64) {
        float* row = sc + tid * 66;
        float mx = row[0];
        for (int j = 1; j < 65; ++j) mx = fmaxf(mx, row[j]);
        float sum = 0.f;
        for (int j = 0; j < 65; ++j) {
            float ex = expf(row[j] - mx);
            row[j] = ex;
            sum += ex;
        }
        float inv = 1.f / sum;
        for (int j = 0; j < 65; ++j) row[j] *= inv;
    }
    __syncthreads();

    // ---- phase 1 AV: row-union — each V row loaded once per warp ----
    ull lo_[4][2];
#pragma unroll
    for (int iq = 0; iq < 4; ++iq) lo_[iq][0] = lo_[iq][1] = 0;
    {
        const int qb = w * 4;
        for (int rr = 0; rr < 68; ++rr) {
            const ull* v2 = (const ull*)(sv + (qb + rr) * 128 + lane * 4);
            ull v0 = v2[0], v1 = v2[1];
#pragma unroll
            for (int iq = 0; iq < 4; ++iq) {
                int jj = rr - iq;
                if (jj >= 0 && jj <= 64) {
                    ull wt2 = dup2(sc[(qb + iq) * 66 + jj]);
                    lo_[iq][0] = fma2(wt2, v0, lo_[iq][0]);
                    lo_[iq][1] = fma2(wt2, v1, lo_[iq][1]);
                }
            }
        }
    }
    __syncthreads();

    // ---- phase 2: landmark K/V ----
#pragma unroll
    for (int it = 0; it < 4; ++it) {
        int idx = tid + it * 512;
        int r = idx >> 5, c4 = idx & 31;
        int pos = r * 64;
        *(float4*)&sk[r * KP + c4 * 4] =
            *(const float4*)&K[(size_t)pos * (NKV * DH) + kvh * DH + c4 * 4];
        *(float4*)&sv[r * 128 + c4 * 4] =
            *(const float4*)&V[(size_t)pos * (NKV * DH) + kvh * DH + c4 * 4];
    }
    __syncthreads();

    const int nvis = n + 1;
    {
        const int i = tid >> 3;
        const int jo = tid & 7;
        ull s2[8];
#pragma unroll
        for (int m = 0; m < 8; ++m) s2[m] = 0;
        const float* qrow = sq + i * QP;
        for (int d0 = 0; d0 < 128; d0 += 8) {
            ull q2[4];
            q2[0] = *(const ull*)&qrow[d0];
            q2[1] = *(const ull*)&qrow[d0 + 2];
            q2[2] = *(const ull*)&qrow[d0 + 4];
            q2[3] = *(const ull*)&qrow[d0 + 6];
#pragma unroll
            for (int m = 0; m < 8; ++m) {
                const ull* kr = (const ull*)(sk + (jo + 8 * m) * KP + d0);
#pragma unroll
                for (int dd = 0; dd < 4; ++dd) s2[m] = fma2(q2[dd], kr[dd], s2[m]);
            }
        }
#pragma unroll
        for (int m = 0; m < 8; ++m) {
            int jj = jo + 8 * m;
            if (jj < nvis) sc[i * 66 + jj] = lo2(s2[m]) * ATT_SCALE;
        }
    }
    __syncthreads();

    if (tid < 64) {
        float* row = sc + tid * 66;
        float mx = row[0];
        for (int j = 1; j < nvis; ++j) mx = fmaxf(mx, row[j]);
        float sum = 0.f;
        for (int j = 0; j < nvis; ++j) {
            float ex = expf(row[j] - mx);
            row[j] = ex;
            sum += ex;
        }
        float inv = 1.f / sum;
        for (int j = 0; j < nvis; ++j) row[j] *= inv;
    }
    __syncthreads();

    // ---- phase 2 AV: V row hoisted (query-independent) + combine + store ----
    {
        ull go[4][2];
#pragma unroll
        for (int iq = 0; iq < 4; ++iq) go[iq][0] = go[iq][1] = 0;
        const int qb = w * 4;
        for (int jj = 0; jj < nvis; ++jj) {
            const ull* v2 = (const ull*)(sv + jj * 128 + lane * 4);
            ull v0 = v2[0], v1 = v2[1];
#pragma unroll
            for (int iq = 0; iq < 4; ++iq) {
                ull wt2 = dup2(sc[(qb + iq) * 66 + jj]);
                go[iq][0] = fma2(wt2, v0, go[iq][0]);
                go[iq][1] = fma2(wt2, v1, go[iq][1]);
            }
        }
#pragma unroll
        for (int iq = 0; iq < 4; ++iq) {
            const int i = qb + iq;
            float2 ga = unp2(go[iq][0]), gb = unp2(go[iq][1]);
            float2 la = unp2(lo_[iq][0]), lb = unp2(lo_[iq][1]);
            float s4[4] = {0.7f * la.x + 0.3f * ga.x, 0.7f * la.y + 0.3f * ga.y,
                           0.7f * lb.x + 0.3f * gb.x, 0.7f * lb.y + 0.3f * gb.y};
            size_t idx = (size_t)(q0 + i) * (NH * DH) + h * DH + lane * 4;
            union { __half b2[4]; uint2 u; } H, L;
#pragma unroll
            for (int q = 0; q < 4; ++q) {
                __half hb = __float2half_rn(s4[q]);
                H.b2[q] = hb;
                L.b2[q] = __float2half_rn(s4[q] - __half2float(hb));
            }
            *(uint2*)&atHi[idx] = H.u;
            *(uint2*)&atLo[idx] = L.u;
        }
    }
}

// ---------------- launch ----------------
extern "C" void kernel_launch(void* const* d_in, const int* in_sizes, int n_in,
                              void* d_out, int out_size) {
    const float* hs = (const float*)d_in[0];
    const float* wq = (const float*)d_in[1];
    const float* wk = (const float*)d_in[2];
    const float* wv = (const float*)d_in[3];
    const float* wo = (const float*)d_in[4];
    float* out = (float*)d_out;

    float *Q, *K, *V;
    __nv_bfloat16 *hsHi, *hsLo, *wqkTHi, *wqkTLo;
    __half *hs16h, *hs16l, *wvT16, *woT16, *at16h, *at16l;
    cudaGetSymbolAddress((void**)&Q, g_Q);
    cudaGetSymbolAddress((void**)&K, g_K);
    cudaGetSymbolAddress((void**)&V, g_V);
    cudaGetSymbolAddress((void**)&hsHi, g_hsHi);
    cudaGetSymbolAddress((void**)&hsLo, g_hsLo);
    cudaGetSymbolAddress((void**)&hs16h, g_hs16h);
    cudaGetSymbolAddress((void**)&hs16l, g_hs16l);
    cudaGetSymbolAddress((void**)&wqkTHi, g_wqkTHi);
    cudaGetSymbolAddress((void**)&wqkTLo, g_wqkTLo);
    cudaGetSymbolAddress((void**)&wvT16, g_wvT16);
    cudaGetSymbolAddress((void**)&woT16, g_woT16);
    cudaGetSymbolAddress((void**)&at16h, g_at16h);
    cudaGetSymbolAddress((void**)&at16l, g_at16l);

    const int SMEM_ATT = (64 * QP + 128 * KP + 128 * 128 + 64 * 66) * 4;
    const int SMEM_G3 = 2 * (32768 + 16384);
    const int SMEM_G2 = 2 * (32768 + 8192);
    cudaFuncSetAttribute(fused_attn_kernel, cudaFuncAttributeMaxDynamicSharedMemorySize, SMEM_ATT);
    cudaFuncSetAttribute(gemm_tc<__nv_bfloat16, true>,
                         cudaFuncAttributeMaxDynamicSharedMemorySize, SMEM_G3);
    cudaFuncSetAttribute(gemm_tc<__half, false>,
                         cudaFuncAttributeMaxDynamicSharedMemorySize, SMEM_G2);

    // conversions feeding QK gemm
    split_all_kernel<<<(S_LEN * HID) / 1024, 256>>>(hs, hsHi, hsLo, hs16h, hs16l);
    transpose_split_kernel<<<dim3(HID / 32, HID / 32), dim3(32, 8)>>>(
        wq, wqkTHi, wqkTLo, HID, HID);
    transpose_split_kernel<<<dim3((NKV * DH) / 32, HID / 32), dim3(32, 8)>>>(
        wk, wqkTHi + (size_t)HID * HID, wqkTLo + (size_t)HID * HID, HID, NKV * DH);

    // fused Q+K gemm (ncu capture slot 4)
    gemm_tc<__nv_bfloat16, true><<<dim3((HID + NKV * DH) / 64, S_LEN / 128), 256, SMEM_G3>>>(
        hsHi, hsLo, wqkTHi, wqkTLo, Q, K, NH * DH, NKV * DH, HID);

    transpose_f16_kernel<<<dim3((NKV * DH) / 32, HID / 32), dim3(32, 8)>>>(wv, wvT16, HID, NKV * DH);
    gemm_tc<__half, false><<<dim3((NKV * DH) / 64, S_LEN / 128), 256, SMEM_G2>>>(
        hs16h, hs16l, wvT16, (const __half*)nullptr, V, V, NKV * DH, 0, HID);

    transpose_f16_kernel<<<dim3(HID / 32, HID / 32), dim3(32, 8)>>>(wo, woT16, HID, HID);

    rope_kernel<<<S_LEN, 64>>>(Q, NH);
    rope_kernel<<<S_LEN, 64>>>(K, NKV);

    fused_attn_kernel<<<dim3(S_LEN / 64, NH), 512, SMEM_ATT>>>(Q, K, V, at16h, at16l);

    gemm_tc<__half, false><<<dim3(HID / 64, S_LEN / 128), 256, SMEM_G2>>>(
        at16h, at16l, woT16, (const __half*)nullptr, out, out, HID, 0, HID);
}

// round 14
// speedup vs baseline: 1.1487x; 1.0400x over previous
#include <cuda_runtime.h>
#include <cuda_bf16.h>
#include <cuda_fp16.h>
#include <math.h>
#include <stdint.h>

#define S_LEN 4096
#define HID 4096
#define NH 32
#define NKV 8
#define DH 128
#define ATT_SCALE 0.08838834764831845f  // 1/sqrt(128)

// ---------------- scratch ----------------
__device__ float g_Q[S_LEN * NH * DH];
__device__ float g_K[S_LEN * NKV * DH];
__device__ float g_V[S_LEN * NKV * DH];
__device__ __nv_bfloat16 g_hsHi[S_LEN * HID];
__device__ __nv_bfloat16 g_hsLo[S_LEN * HID];
__device__ __half g_hs16h[S_LEN * HID];
__device__ __half g_hs16l[S_LEN * HID];
__device__ __nv_bfloat16 g_wqkTHi[(HID + NKV * DH) * HID];
__device__ __nv_bfloat16 g_wqkTLo[(HID + NKV * DH) * HID];
__device__ __half g_wvT16[(NKV * DH) * HID];
__device__ __half g_woT16[HID * HID];
__device__ __half g_at16h[S_LEN * NH * DH];
__device__ __half g_at16l[S_LEN * NH * DH];

// ================= helpers =================
__device__ __forceinline__ uint32_t smem_u32(const void* p) {
    uint32_t a;
    asm("{ .reg .u64 t; cvta.to.shared.u64 t, %1; cvt.u32.u64 %0, t; }" : "=r"(a) : "l"(p));
    return a;
}
__device__ __forceinline__ uint32_t swz(uint32_t o) { return o ^ ((o >> 3) & 0x70); }

__device__ __forceinline__ void ldsm_x4(uint32_t& r0, uint32_t& r1, uint32_t& r2, uint32_t& r3,
                                        uint32_t addr) {
    asm volatile("ldmatrix.sync.aligned.m8n8.x4.shared.b16 {%0, %1, %2, %3}, [%4];"
                 : "=r"(r0), "=r"(r1), "=r"(r2), "=r"(r3) : "r"(addr));
}

template <typename T> struct MmaOp;
template <> struct MmaOp<__nv_bfloat16> {
    static __device__ __forceinline__ void run(float* c, const uint32_t* a, uint32_t b0,
                                               uint32_t b1) {
        asm volatile(
            "mma.sync.aligned.m16n8k16.row.col.f32.bf16.bf16.f32 "
            "{%0, %1, %2, %3}, {%4, %5, %6, %7}, {%8, %9}, {%0, %1, %2, %3};"
            : "+f"(c[0]), "+f"(c[1]), "+f"(c[2]), "+f"(c[3])
            : "r"(a[0]), "r"(a[1]), "r"(a[2]), "r"(a[3]), "r"(b0), "r"(b1));
    }
};
template <> struct MmaOp<__half> {
    static __device__ __forceinline__ void run(float* c, const uint32_t* a, uint32_t b0,
                                               uint32_t b1) {
        asm volatile(
            "mma.sync.aligned.m16n8k16.row.col.f32.f16.f16.f32 "
            "{%0, %1, %2, %3}, {%4, %5, %6, %7}, {%8, %9}, {%0, %1, %2, %3};"
            : "+f"(c[0]), "+f"(c[1]), "+f"(c[2]), "+f"(c[3])
            : "r"(a[0]), "r"(a[1]), "r"(a[2]), "r"(a[3]), "r"(b0), "r"(b1));
    }
};

__device__ __forceinline__ void cp16(uint32_t dst, const void* src) {
    asm volatile("cp.async.cg.shared.global [%0], [%1], 16;" :: "r"(dst), "l"(src));
}
#define CP_COMMIT() asm volatile("cp.async.commit_group;" ::: "memory")
#define CP_WAIT1() asm volatile("cp.async.wait_group 1;" ::: "memory")

// packed f32x2
typedef unsigned long long ull;
__device__ __forceinline__ ull fma2(ull a, ull b, ull c) {
    ull d;
    asm("fma.rn.f32x2 %0, %1, %2, %3;" : "=l"(d) : "l"(a), "l"(b), "l"(c));
    return d;
}
__device__ __forceinline__ ull dup2(float a) {
    ull d;
    asm("mov.b64 %0, {%1, %1};" : "=l"(d) : "f"(a));
    return d;
}
__device__ __forceinline__ float lo2(ull a) {
    float x, y;
    asm("mov.b64 {%0, %1}, %2;" : "=f"(x), "=f"(y) : "l"(a));
    return x + y;
}
__device__ __forceinline__ float2 unp2(ull a) {
    float2 r;
    asm("mov.b64 {%0, %1}, %2;" : "=f"(r.x), "=f"(r.y) : "l"(a));
    return r;
}

// ================= conversion kernels =================
__global__ void split_all_kernel(const float* __restrict__ in,
                                 __nv_bfloat16* __restrict__ hi,
                                 __nv_bfloat16* __restrict__ lo,
                                 __half* __restrict__ h16,
                                 __half* __restrict__ l16) {
    int i = (blockIdx.x * 256 + threadIdx.x) * 4;
    float4 v = *(const float4*)&in[i];
    float f[4] = {v.x, v.y, v.z, v.w};
    union { __nv_bfloat16 b[4]; uint2 u; } H, L;
    union { __half b[4]; uint2 u; } H16, L16;
#pragma unroll
    for (int j = 0; j < 4; ++j) {
        __nv_bfloat16 h = __float2bfloat16(f[j]);
        H.b[j] = h;
        L.b[j] = __float2bfloat16(f[j] - __bfloat162float(h));
        __half p = __float2half_rn(f[j]);
        H16.b[j] = p;
        L16.b[j] = __float2half_rn(f[j] - __half2float(p));
    }
    *(uint2*)&hi[i] = H.u;
    *(uint2*)&lo[i] = L.u;
    *(uint2*)&h16[i] = H16.u;
    *(uint2*)&l16[i] = L16.u;
}

__global__ void transpose_split_kernel(const float* __restrict__ W,
                                       __nv_bfloat16* __restrict__ hi,
                                       __nv_bfloat16* __restrict__ lo,
                                       int rows, int cols) {
    __shared__ float t[32][33];
    int c0 = blockIdx.x * 32, r0 = blockIdx.y * 32;
    int tx = threadIdx.x, ty = threadIdx.y;
#pragma unroll
    for (int j = 0; j < 4; ++j) {
        int r = ty + j * 8;
        t[r][tx] = W[(size_t)(r0 + r) * cols + c0 + tx];
    }
    __syncthreads();
#pragma unroll
    for (int j = 0; j < 4; ++j) {
        int r = ty + j * 8;
        float v = t[tx][r];
        __nv_bfloat16 h = __float2bfloat16(v);
        size_t o = (size_t)(c0 + r) * rows + r0 + tx;
        hi[o] = h;
        lo[o] = __float2bfloat16(v - __bfloat162float(h));
    }
}

__global__ void transpose_f16_kernel(const float* __restrict__ W,
                                     __half* __restrict__ out, int rows, int cols) {
    __shared__ float t[32][33];
    int c0 = blockIdx.x * 32, r0 = blockIdx.y * 32;
    int tx = threadIdx.x, ty = threadIdx.y;
#pragma unroll
    for (int j = 0; j < 4; ++j) {
        int r = ty + j * 8;
        t[r][tx] = W[(size_t)(r0 + r) * cols + c0 + tx];
    }
    __syncthreads();
#pragma unroll
    for (int j = 0; j < 4; ++j) {
        int r = ty + j * 8;
        out[(size_t)(c0 + r) * rows + r0 + tx] = __float2half_rn(t[tx][r]);
    }
}

// ================= HMMA GEMM (R8 geometry, dual-output epilogue) =================
template <typename T, bool SPLIT_B>
__global__ __launch_bounds__(256, 2)
void gemm_tc(const T* __restrict__ Ahi, const T* __restrict__ Alo,
             const T* __restrict__ Bhi, const T* __restrict__ Blo,
             float* __restrict__ C0, float* __restrict__ C1,
             int N0, int N1, int K) {
    constexpr uint32_t B_OFF = 32768;
    constexpr uint32_t STG = B_OFF + (SPLIT_B ? 16384 : 8192);
    extern __shared__ char smem[];
    const uint32_t sb = smem_u32(smem);
    const int tid = threadIdx.x, lane = tid & 31, wid = tid >> 5;
    const int m0 = blockIdx.y * 128, n0 = blockIdx.x * 64;
    const int wm = (wid >> 1) * 32, wn = (wid & 1) * 32;

    const T* aptr[4];
    uint32_t asw[4];
#pragma unroll
    for (int i = 0; i < 4; ++i) {
        int idx = tid + (i << 8);
        int r = idx >> 3, c = idx & 7;
        aptr[i] = Ahi + (size_t)(m0 + r) * K + (c << 3);
        asw[i] = swz(r * 128 + c * 16);
    }
    const T* bptr[2];
    uint32_t bsw[2];
#pragma unroll
    for (int i = 0; i < 2; ++i) {
        int idx = tid + (i << 8);
        int r = idx >> 3, c = idx & 7;
        bptr[i] = Bhi + (size_t)(n0 + r) * K + (c << 3);
        bsw[i] = swz(r * 128 + c * 16);
    }
    const ptrdiff_t dA = Alo - Ahi;
    const ptrdiff_t dB = SPLIT_B ? (Blo - Bhi) : 0;

    float acc[2][4][4];
#pragma unroll
    for (int mt = 0; mt < 2; ++mt)
#pragma unroll
        for (int nt = 0; nt < 4; ++nt)
#pragma unroll
            for (int q = 0; q < 4; ++q) acc[mt][nt][q] = 0.f;

    const int NKT = K >> 6;
#pragma unroll
    for (int s = 0; s < 2; ++s) {
        const uint32_t st = sb + s * STG;
        const int ko = s * 64;
#pragma unroll
        for (int i = 0; i < 4; ++i) {
            cp16(st + asw[i], aptr[i] + ko);
            cp16(st + 16384 + asw[i], aptr[i] + dA + ko);
        }
#pragma unroll
        for (int i = 0; i < 2; ++i) {
            cp16(st + B_OFF + bsw[i], bptr[i] + ko);
            if (SPLIT_B) cp16(st + B_OFF + 8192 + bsw[i], bptr[i] + dB + ko);
        }
        CP_COMMIT();
    }

    const int row_off = ((lane >> 3) & 1) * 8 + (lane & 7);
    const int kxtra = (lane >> 4) * 16;
    const uint32_t a_lb = (uint32_t)((wm + row_off) * 128 + kxtra);
    const uint32_t b_lb = (uint32_t)((wn + row_off) * 128 + kxtra);

    for (int kt = 0; kt < NKT; ++kt) {
        CP_WAIT1();
        __syncthreads();
        const uint32_t st = sb + (uint32_t)(kt & 1) * STG;
#pragma unroll
        for (int ks = 0; ks < 4; ++ks) {
            uint32_t ah[2][4], al[2][4], bh[2][4];
#pragma unroll
            for (int mt = 0; mt < 2; ++mt) {
                uint32_t off = swz(a_lb + mt * 16 * 128 + ks * 32);
                ldsm_x4(ah[mt][0], ah[mt][1], ah[mt][2], ah[mt][3], st + off);
                ldsm_x4(al[mt][0], al[mt][1], al[mt][2], al[mt][3], st + 16384 + off);
            }
#pragma unroll
            for (int nt2 = 0; nt2 < 2; ++nt2)
                ldsm_x4(bh[nt2][0], bh[nt2][1], bh[nt2][2], bh[nt2][3],
                        st + B_OFF + swz(b_lb + nt2 * 16 * 128 + ks * 32));
            if (SPLIT_B) {
                uint32_t bl[2][4];
#pragma unroll
                for (int nt2 = 0; nt2 < 2; ++nt2)
                    ldsm_x4(bl[nt2][0], bl[nt2][1], bl[nt2][2], bl[nt2][3],
                            st + B_OFF + 8192 + swz(b_lb + nt2 * 16 * 128 + ks * 32));
#pragma unroll
                for (int mt = 0; mt < 2; ++mt)
#pragma unroll
                    for (int nt = 0; nt < 4; ++nt) {
                        MmaOp<T>::run(acc[mt][nt], ah[mt],
                                      bh[nt >> 1][nt & 1], bh[nt >> 1][2 + (nt & 1)]);
                        MmaOp<T>::run(acc[mt][nt], ah[mt],
                                      bl[nt >> 1][nt & 1], bl[nt >> 1][2 + (nt & 1)]);
                        MmaOp<T>::run(acc[mt][nt], al[mt],
                                      bh[nt >> 1][nt & 1], bh[nt >> 1][2 + (nt & 1)]);
                    }
            } else {
#pragma unroll
                for (int mt = 0; mt < 2; ++mt)
#pragma unroll
                    for (int nt = 0; nt < 4; ++nt) {
                        MmaOp<T>::run(acc[mt][nt], ah[mt],
                                      bh[nt >> 1][nt & 1], bh[nt >> 1][2 + (nt & 1)]);
                        MmaOp<T>::run(acc[mt][nt], al[mt],
                                      bh[nt >> 1][nt & 1], bh[nt >> 1][2 + (nt & 1)]);
                    }
            }
        }
        __syncthreads();
        if (kt + 2 < NKT) {
            const uint32_t st2 = sb + (uint32_t)(kt & 1) * STG;
            const int ko = (kt + 2) * 64;
#pragma unroll
            for (int i = 0; i < 4; ++i) {
                cp16(st2 + asw[i], aptr[i] + ko);
                cp16(st2 + 16384 + asw[i], aptr[i] + dA + ko);
            }
#pragma unroll
            for (int i = 0; i < 2; ++i) {
                cp16(st2 + B_OFF + bsw[i], bptr[i] + ko);
                if (SPLIT_B) cp16(st2 + B_OFF + 8192 + bsw[i], bptr[i] + dB + ko);
            }
        }
        CP_COMMIT();
    }

    float* Cc;
    int Nc, col0;
    if (n0 < N0) {
        Cc = C0; Nc = N0; col0 = n0;
    } else {
        Cc = C1; Nc = N1; col0 = n0 - N0;
    }
#pragma unroll
    for (int mt = 0; mt < 2; ++mt) {
        const int row = m0 + wm + mt * 16 + (lane >> 2);
#pragma unroll
        for (int nt = 0; nt < 4; ++nt) {
            const int col = col0 + wn + nt * 8 + (lane & 3) * 2;
            float* p0 = Cc + (size_t)row * Nc + col;
            *(float2*)p0 = make_float2(acc[mt][nt][0], acc[mt][nt][1]);
            *(float2*)(p0 + 8 * (size_t)Nc) = make_float2(acc[mt][nt][2], acc[mt][nt][3]);
        }
    }
}

// ---------------- RoPE ----------------
__global__ void rope_kernel(float* __restrict__ X, int nh) {
    const int s = blockIdx.x;
    const int d = threadIdx.x;
    const float e = (float)d * (1.0f / 64.0f);
    const float invf = 1.0f / powf(10000.0f, e);
    const float ang = (float)s * invf;
    float sn, cs;
    sincosf(ang, &sn, &cs);
    float* p = X + (size_t)s * nh * DH;
    for (int h = 0; h < nh; ++h) {
        const float x1 = p[d];
        const float x2 = p[d + 64];
        p[d] = x1 * cs - x2 * sn;
        p[d + 64] = x2 * cs + x1 * sn;
        p += DH;
    }
}

// ---------------- fused attention (query-pair score blocking + row-union AV) ----------------
#define QP 132
#define KP 132
__global__ __launch_bounds__(512, 1)
void fused_attn_kernel(const float* __restrict__ Q, const float* __restrict__ K,
                       const float* __restrict__ V,
                       __half* __restrict__ atHi, __half* __restrict__ atLo) {
    extern __shared__ float sm[];
    float* sq = sm;                 // 64 x 132
    float* sk = sq + 64 * QP;       // 128 x 132 (phase2: landmark K)
    float* sv = sk + 128 * KP;      // 128 x 128 (phase2: landmark V)
    float* sc = sv + 128 * 128;     // 64 x 66

    const int tid = threadIdx.x;
    const int h = blockIdx.y;
    const int n = blockIdx.x;
    const int kvh = h >> 2;
    const int q0 = n * 64;
    const int key0 = q0 - 64;
    const int w = tid >> 5, lane = tid & 31;

#pragma unroll
    for (int it = 0; it < 4; ++it) {
        int idx = tid + it * 512;
        int r = idx >> 5, c4 = idx & 31;
        float4 v4 = *(const float4*)&Q[(size_t)(q0 + r) * (NH * DH) + h * DH + c4 * 4];
        *(float4*)&sq[r * QP + c4 * 4] = v4;
    }
#pragma unroll
    for (int it = 0; it < 8; ++it) {
        int idx = tid + it * 512;
        int r = idx >> 5, c4 = idx & 31;
        int pos = key0 + r;
        float4 kv = make_float4(0.f, 0.f, 0.f, 0.f);
        float4 vv = make_float4(0.f, 0.f, 0.f, 0.f);
        if (pos >= 0) {
            kv = *(const float4*)&K[(size_t)pos * (NKV * DH) + kvh * DH + c4 * 4];
            vv = *(const float4*)&V[(size_t)pos * (NKV * DH) + kvh * DH + c4 * 4];
        }
        *(float4*)&sk[r * KP + c4 * 4] = kv;
        *(float4*)&sv[r * 128 + c4 * 4] = vv;
    }
    __syncthreads();

    // ---- phase 1 scores: query-pair blocking (K row shared by 2 queries) ----
    {
        const int i2 = tid >> 4;        // 0..31 query pair
        const int jo = tid & 15;        // 0..15
        const int qa = 2 * i2, qb = qa + 1;
        ull sa[4], sb[4];
        ull sx0 = 0, sx1 = 0, sx2 = 0;
#pragma unroll
        for (int m = 0; m < 4; ++m) sa[m] = sb[m] = 0;
        const float* qra = sq + qa * QP;
        const float* qrb = sq + qb * QP;
        for (int d0 = 0; d0 < 128; d0 += 8) {
            ull qav[4], qbv[4];
#pragma unroll
            for (int u = 0; u < 4; ++u) {
                qav[u] = *(const ull*)&qra[d0 + 2 * u];
                qbv[u] = *(const ull*)&qrb[d0 + 2 * u];
            }
#pragma unroll
            for (int m = 0; m < 4; ++m) {
                const ull* kr = (const ull*)(sk + (qa + jo + 16 * m) * KP + d0);
                ull k0 = kr[0], k1 = kr[1], k2 = kr[2], k3 = kr[3];
                sa[m] = fma2(qav[0], k0, sa[m]);
                sa[m] = fma2(qav[1], k1, sa[m]);
                sa[m] = fma2(qav[2], k2, sa[m]);
                sa[m] = fma2(qav[3], k3, sa[m]);
                sb[m] = fma2(qbv[0], k0, sb[m]);
                sb[m] = fma2(qbv[1], k1, sb[m]);
                sb[m] = fma2(qbv[2], k2, sb[m]);
                sb[m] = fma2(qbv[3], k3, sb[m]);
            }
            if (jo == 0) {
                const ull* kr = (const ull*)(sk + (qa + 64) * KP + d0);
#pragma unroll
                for (int u = 0; u < 4; ++u) {
                    sx0 = fma2(qav[u], kr[u], sx0);
                    sx1 = fma2(qbv[u], kr[u], sx1);
                }
            }
            if (jo == 1) {
                const ull* kr = (const ull*)(sk + (qa + 65) * KP + d0);
#pragma unroll
                for (int u = 0; u < 4; ++u) sx2 = fma2(qbv[u], kr[u], sx2);
            }
        }
#pragma unroll
        for (int m = 0; m < 4; ++m) {
            int jja = jo + 16 * m;
            sc[qa * 66 + jja] = lo2(sa[m]) * ATT_SCALE;
            int jjb = jja - 1;
            if (jjb >= 0) sc[qb * 66 + jjb] = lo2(sb[m]) * ATT_SCALE;
        }
        if (jo == 0) {
            sc[qa * 66 + 64] = lo2(sx0) * ATT_SCALE;
            sc[qb * 66 + 63] = lo2(sx1) * ATT_SCALE;
        }
        if (jo == 1) sc[qb * 66 + 64] = lo2(sx2) * ATT_SCALE;
    }
    __syncthreads();

    if (tid < 64) {
        float* row = sc + tid * 66;
        float mx = row[0];
        for (int j = 1; j < 65; ++j) mx = fmaxf(mx, row[j]);
        float sum = 0.f;
        for (int j = 0; j < 65; ++j) {
            float ex = expf(row[j] - mx);
            row[j] = ex;
            sum += ex;
        }
        float inv = 1.f / sum;
        for (int j = 0; j < 65; ++j) row[j] *= inv;
    }
    __syncthreads();

    // ---- phase 1 AV: row-union ----
    ull lo_[4][2];
#pragma unroll
    for (int iq = 0; iq < 4; ++iq) lo_[iq][0] = lo_[iq][1] = 0;
    {
        const int qb2 = w * 4;
        for (int rr = 0; rr < 68; ++rr) {
            const ull* v2 = (const ull*)(sv + (qb2 + rr) * 128 + lane * 4);
            ull v0 = v2[0], v1 = v2[1];
#pragma unroll
            for (int iq = 0; iq < 4; ++iq) {
                int jj = rr - iq;
                if (jj >= 0 && jj <= 64) {
                    ull wt2 = dup2(sc[(qb2 + iq) * 66 + jj]);
                    lo_[iq][0] = fma2(wt2, v0, lo_[iq][0]);
                    lo_[iq][1] = fma2(wt2, v1, lo_[iq][1]);
                }
            }
        }
    }
    __syncthreads();

    // ---- phase 2: landmark K/V ----
#pragma unroll
    for (int it = 0; it < 4; ++it) {
        int idx = tid + it * 512;
        int r = idx >> 5, c4 = idx & 31;
        int pos = r * 64;
        *(float4*)&sk[r * KP + c4 * 4] =
            *(const float4*)&K[(size_t)pos * (NKV * DH) + kvh * DH + c4 * 4];
        *(float4*)&sv[r * 128 + c4 * 4] =
            *(const float4*)&V[(size_t)pos * (NKV * DH) + kvh * DH + c4 * 4];
    }
    __syncthreads();

    const int nvis = n + 1;
    // ---- phase 2 scores: query-pair blocking + nvis bound ----
    {
        const int i2 = tid >> 4;
        const int jo = tid & 15;
        const int qa = 2 * i2, qb = qa + 1;
        ull s2[4][2];
#pragma unroll
        for (int m = 0; m < 4; ++m) s2[m][0] = s2[m][1] = 0;
        const float* qra = sq + qa * QP;
        const float* qrb = sq + qb * QP;
        for (int d0 = 0; d0 < 128; d0 += 8) {
            ull qav[4], qbv[4];
#pragma unroll
            for (int u = 0; u < 4; ++u) {
                qav[u] = *(const ull*)&qra[d0 + 2 * u];
                qbv[u] = *(const ull*)&qrb[d0 + 2 * u];
            }
#pragma unroll
            for (int m = 0; m < 4; ++m) {
                int key = jo + 16 * m;
                if (key < nvis) {
                    const ull* kr = (const ull*)(sk + key * KP + d0);
                    ull k0 = kr[0], k1 = kr[1], k2 = kr[2], k3 = kr[3];
                    s2[m][0] = fma2(qav[0], k0, s2[m][0]);
                    s2[m][0] = fma2(qav[1], k1, s2[m][0]);
                    s2[m][0] = fma2(qav[2], k2, s2[m][0]);
                    s2[m][0] = fma2(qav[3], k3, s2[m][0]);
                    s2[m][1] = fma2(qbv[0], k0, s2[m][1]);
                    s2[m][1] = fma2(qbv[1], k1, s2[m][1]);
                    s2[m][1] = fma2(qbv[2], k2, s2[m][1]);
                    s2[m][1] = fma2(qbv[3], k3, s2[m][1]);
                }
            }
        }
#pragma unroll
        for (int m = 0; m < 4; ++m) {
            int key = jo + 16 * m;
            if (key < nvis) {
                sc[qa * 66 + key] = lo2(s2[m][0]) * ATT_SCALE;
                sc[qb * 66 + key] = lo2(s2[m][1]) * ATT_SCALE;
            }
        }
    }
    __syncthreads();

    if (tid < 64) {
        float* row = sc + tid * 66;
        float mx = row[0];
        for (int j = 1; j < nvis; ++j) mx = fmaxf(mx, row[j]);
        float sum = 0.f;
        for (int j = 0; j < nvis; ++j) {
            float ex = expf(row[j] - mx);
            row[j] = ex;
            sum += ex;
        }
        float inv = 1.f / sum;
        for (int j = 0; j < nvis; ++j) row[j] *= inv;
    }
    __syncthreads();

    // ---- phase 2 AV (V row hoisted) + combine + store ----
    {
        ull go[4][2];
#pragma unroll
        for (int iq = 0; iq < 4; ++iq) go[iq][0] = go[iq][1] = 0;
        const int qb2 = w * 4;
        for (int jj = 0; jj < nvis; ++jj) {
            const ull* v2 = (const ull*)(sv + jj * 128 + lane * 4);
            ull v0 = v2[0], v1 = v2[1];
#pragma unroll
            for (int iq = 0; iq < 4; ++iq) {
                ull wt2 = dup2(sc[(qb2 + iq) * 66 + jj]);
                go[iq][0] = fma2(wt2, v0, go[iq][0]);
                go[iq][1] = fma2(wt2, v1, go[iq][1]);
            }
        }
#pragma unroll
        for (int iq = 0; iq < 4; ++iq) {
            const int i = qb2 + iq;
            float2 ga = unp2(go[iq][0]), gb = unp2(go[iq][1]);
            float2 la = unp2(lo_[iq][0]), lb = unp2(lo_[iq][1]);
            float s4[4] = {0.7f * la.x + 0.3f * ga.x, 0.7f * la.y + 0.3f * ga.y,
                           0.7f * lb.x + 0.3f * gb.x, 0.7f * lb.y + 0.3f * gb.y};
            size_t idx = (size_t)(q0 + i) * (NH * DH) + h * DH + lane * 4;
            union { __half b2[4]; uint2 u; } H, L;
#pragma unroll
            for (int q = 0; q < 4; ++q) {
                __half hb = __float2half_rn(s4[q]);
                H.b2[q] = hb;
                L.b2[q] = __float2half_rn(s4[q] - __half2float(hb));
            }
            *(uint2*)&atHi[idx] = H.u;
            *(uint2*)&atLo[idx] = L.u;
        }
    }
}

// ---------------- launch ----------------
extern "C" void kernel_launch(void* const* d_in, const int* in_sizes, int n_in,
                              void* d_out, int out_size) {
    const float* hs = (const float*)d_in[0];
    const float* wq = (const float*)d_in[1];
    const float* wk = (const float*)d_in[2];
    const float* wv = (const float*)d_in[3];
    const float* wo = (const float*)d_in[4];
    float* out = (float*)d_out;

    float *Q, *K, *V;
    __nv_bfloat16 *hsHi, *hsLo, *wqkTHi, *wqkTLo;
    __half *hs16h, *hs16l, *wvT16, *woT16, *at16h, *at16l;
    cudaGetSymbolAddress((void**)&Q, g_Q);
    cudaGetSymbolAddress((void**)&K, g_K);
    cudaGetSymbolAddress((void**)&V, g_V);
    cudaGetSymbolAddress((void**)&hsHi, g_hsHi);
    cudaGetSymbolAddress((void**)&hsLo, g_hsLo);
    cudaGetSymbolAddress((void**)&hs16h, g_hs16h);
    cudaGetSymbolAddress((void**)&hs16l, g_hs16l);
    cudaGetSymbolAddress((void**)&wqkTHi, g_wqkTHi);
    cudaGetSymbolAddress((void**)&wqkTLo, g_wqkTLo);
    cudaGetSymbolAddress((void**)&wvT16, g_wvT16);
    cudaGetSymbolAddress((void**)&woT16, g_woT16);
    cudaGetSymbolAddress((void**)&at16h, g_at16h);
    cudaGetSymbolAddress((void**)&at16l, g_at16l);

    const int SMEM_ATT = (64 * QP + 128 * KP + 128 * 128 + 64 * 66) * 4;
    const int SMEM_G3 = 2 * (32768 + 16384);
    const int SMEM_G2 = 2 * (32768 + 8192);
    cudaFuncSetAttribute(fused_attn_kernel, cudaFuncAttributeMaxDynamicSharedMemorySize, SMEM_ATT);
    cudaFuncSetAttribute(gemm_tc<__nv_bfloat16, true>,
                         cudaFuncAttributeMaxDynamicSharedMemorySize, SMEM_G3);
    cudaFuncSetAttribute(gemm_tc<__half, false>,
                         cudaFuncAttributeMaxDynamicSharedMemorySize, SMEM_G2);

    // conversions feeding QK gemm
    split_all_kernel<<<(S_LEN * HID) / 1024, 256>>>(hs, hsHi, hsLo, hs16h, hs16l);
    transpose_split_kernel<<<dim3(HID / 32, HID / 32), dim3(32, 8)>>>(
        wq, wqkTHi, wqkTLo, HID, HID);
    transpose_split_kernel<<<dim3((NKV * DH) / 32, HID / 32), dim3(32, 8)>>>(
        wk, wqkTHi + (size_t)HID * HID, wqkTLo + (size_t)HID * HID, HID, NKV * DH);

    // fused Q+K gemm (ncu capture slot 4)
    gemm_tc<__nv_bfloat16, true><<<dim3((HID + NKV * DH) / 64, S_LEN / 128), 256, SMEM_G3>>>(
        hsHi, hsLo, wqkTHi, wqkTLo, Q, K, NH * DH, NKV * DH, HID);

    transpose_f16_kernel<<<dim3((NKV * DH) / 32, HID / 32), dim3(32, 8)>>>(wv, wvT16, HID, NKV * DH);
    gemm_tc<__half, false><<<dim3((NKV * DH) / 64, S_LEN / 128), 256, SMEM_G2>>>(
        hs16h, hs16l, wvT16, (const __half*)nullptr, V, V, NKV * DH, 0, HID);

    transpose_f16_kernel<<<dim3(HID / 32, HID / 32), dim3(32, 8)>>>(wo, woT16, HID, HID);

    rope_kernel<<<S_LEN, 64>>>(Q, NH);
    rope_kernel<<<S_LEN, 64>>>(K, NKV);

    fused_attn_kernel<<<dim3(S_LEN / 64, NH), 512, SMEM_ATT>>>(Q, K, V, at16h, at16l);

    gemm_tc<__half, false><<<dim3(HID / 64, S_LEN / 128), 256, SMEM_G2>>>(
        at16h, at16l, woT16, (const __half*)nullptr, out, out, HID, 0, HID);
}

// round 15
// speedup vs baseline: 1.3693x; 1.1921x over previous
#include <cuda_runtime.h>
#include <cuda_bf16.h>
#include <cuda_fp16.h>
#include <math.h>
#include <stdint.h>

#define S_LEN 4096
#define HID 4096
#define NH 32
#define NKV 8
#define DH 128
#define ATT_SCALE 0.08838834764831845f  // 1/sqrt(128)

// ---------------- scratch ----------------
__device__ float g_Q[S_LEN * NH * DH];
__device__ float g_K[S_LEN * NKV * DH];
__device__ float g_V[S_LEN * NKV * DH];
__device__ __nv_bfloat16 g_hsHi[S_LEN * HID];
__device__ __nv_bfloat16 g_hsLo[S_LEN * HID];
__device__ __half g_hs16h[S_LEN * HID];
__device__ __nv_bfloat16 g_wqkTHi[(HID + NKV * DH) * HID];
__device__ __nv_bfloat16 g_wqkTLo[(HID + NKV * DH) * HID];
__device__ __half g_wvT16[(NKV * DH) * HID];
__device__ __half g_woT16[HID * HID];
__device__ __half g_at16h[S_LEN * NH * DH];

// ================= helpers =================
__device__ __forceinline__ uint32_t smem_u32(const void* p) {
    uint32_t a;
    asm("{ .reg .u64 t; cvta.to.shared.u64 t, %1; cvt.u32.u64 %0, t; }" : "=r"(a) : "l"(p));
    return a;
}
__device__ __forceinline__ uint32_t swz(uint32_t o) { return o ^ ((o >> 3) & 0x70); }

__device__ __forceinline__ void ldsm_x4(uint32_t& r0, uint32_t& r1, uint32_t& r2, uint32_t& r3,
                                        uint32_t addr) {
    asm volatile("ldmatrix.sync.aligned.m8n8.x4.shared.b16 {%0, %1, %2, %3}, [%4];"
                 : "=r"(r0), "=r"(r1), "=r"(r2), "=r"(r3) : "r"(addr));
}

template <typename T> struct MmaOp;
template <> struct MmaOp<__nv_bfloat16> {
    static __device__ __forceinline__ void run(float* c, const uint32_t* a, uint32_t b0,
                                               uint32_t b1) {
        asm volatile(
            "mma.sync.aligned.m16n8k16.row.col.f32.bf16.bf16.f32 "
            "{%0, %1, %2, %3}, {%4, %5, %6, %7}, {%8, %9}, {%0, %1, %2, %3};"
            : "+f"(c[0]), "+f"(c[1]), "+f"(c[2]), "+f"(c[3])
            : "r"(a[0]), "r"(a[1]), "r"(a[2]), "r"(a[3]), "r"(b0), "r"(b1));
    }
};
template <> struct MmaOp<__half> {
    static __device__ __forceinline__ void run(float* c, const uint32_t* a, uint32_t b0,
                                               uint32_t b1) {
        asm volatile(
            "mma.sync.aligned.m16n8k16.row.col.f32.f16.f16.f32 "
            "{%0, %1, %2, %3}, {%4, %5, %6, %7}, {%8, %9}, {%0, %1, %2, %3};"
            : "+f"(c[0]), "+f"(c[1]), "+f"(c[2]), "+f"(c[3])
            : "r"(a[0]), "r"(a[1]), "r"(a[2]), "r"(a[3]), "r"(b0), "r"(b1));
    }
};

__device__ __forceinline__ void cp16(uint32_t dst, const void* src) {
    asm volatile("cp.async.cg.shared.global [%0], [%1], 16;" :: "r"(dst), "l"(src));
}
#define CP_COMMIT() asm volatile("cp.async.commit_group;" ::: "memory")
#define CP_WAIT1() asm volatile("cp.async.wait_group 1;" ::: "memory")

// packed f32x2
typedef unsigned long long ull;
__device__ __forceinline__ ull fma2(ull a, ull b, ull c) {
    ull d;
    asm("fma.rn.f32x2 %0, %1, %2, %3;" : "=l"(d) : "l"(a), "l"(b), "l"(c));
    return d;
}
__device__ __forceinline__ ull dup2(float a) {
    ull d;
    asm("mov.b64 %0, {%1, %1};" : "=l"(d) : "f"(a));
    return d;
}
__device__ __forceinline__ float lo2(ull a) {
    float x, y;
    asm("mov.b64 {%0, %1}, %2;" : "=f"(x), "=f"(y) : "l"(a));
    return x + y;
}
__device__ __forceinline__ float2 unp2(ull a) {
    float2 r;
    asm("mov.b64 {%0, %1}, %2;" : "=f"(r.x), "=f"(r.y) : "l"(a));
    return r;
}

// ================= conversion kernels =================
__global__ void split_all_kernel(const float* __restrict__ in,
                                 __nv_bfloat16* __restrict__ hi,
                                 __nv_bfloat16* __restrict__ lo,
                                 __half* __restrict__ h16) {
    int i = (blockIdx.x * 256 + threadIdx.x) * 4;
    float4 v = *(const float4*)&in[i];
    float f[4] = {v.x, v.y, v.z, v.w};
    union { __nv_bfloat16 b[4]; uint2 u; } H, L;
    union { __half b[4]; uint2 u; } H16;
#pragma unroll
    for (int j = 0; j < 4; ++j) {
        __nv_bfloat16 h = __float2bfloat16(f[j]);
        H.b[j] = h;
        L.b[j] = __float2bfloat16(f[j] - __bfloat162float(h));
        H16.b[j] = __float2half_rn(f[j]);
    }
    *(uint2*)&hi[i] = H.u;
    *(uint2*)&lo[i] = L.u;
    *(uint2*)&h16[i] = H16.u;
}

__global__ void transpose_split_kernel(const float* __restrict__ W,
                                       __nv_bfloat16* __restrict__ hi,
                                       __nv_bfloat16* __restrict__ lo,
                                       int rows, int cols) {
    __shared__ float t[32][33];
    int c0 = blockIdx.x * 32, r0 = blockIdx.y * 32;
    int tx = threadIdx.x, ty = threadIdx.y;
#pragma unroll
    for (int j = 0; j < 4; ++j) {
        int r = ty + j * 8;
        t[r][tx] = W[(size_t)(r0 + r) * cols + c0 + tx];
    }
    __syncthreads();
#pragma unroll
    for (int j = 0; j < 4; ++j) {
        int r = ty + j * 8;
        float v = t[tx][r];
        __nv_bfloat16 h = __float2bfloat16(v);
        size_t o = (size_t)(c0 + r) * rows + r0 + tx;
        hi[o] = h;
        lo[o] = __float2bfloat16(v - __bfloat162float(h));
    }
}

__global__ void transpose_f16_kernel(const float* __restrict__ W,
                                     __half* __restrict__ out, int rows, int cols) {
    __shared__ float t[32][33];
    int c0 = blockIdx.x * 32, r0 = blockIdx.y * 32;
    int tx = threadIdx.x, ty = threadIdx.y;
#pragma unroll
    for (int j = 0; j < 4; ++j) {
        int r = ty + j * 8;
        t[r][tx] = W[(size_t)(r0 + r) * cols + c0 + tx];
    }
    __syncthreads();
#pragma unroll
    for (int j = 0; j < 4; ++j) {
        int r = ty + j * 8;
        out[(size_t)(c0 + r) * rows + r0 + tx] = __float2half_rn(t[tx][r]);
    }
}

// ================= HMMA GEMM =================
// PASSES=3: Ah*Bh + Ah*Bl + Al*Bh (A,B split). PASSES=1: Ah*Bh only.
// CTA 128x64, 256 thr (8 warps 4x2, warp tile 32x32), K-chunk 64, 2-stage, 2 CTAs/SM.
// Dual-output epilogue: cols [0,N0) -> C0, [N0,N0+N1) -> C1.
template <typename T, int PASSES>
__global__ __launch_bounds__(256, 2)
void gemm_tc(const T* __restrict__ Ahi, const T* __restrict__ Alo,
             const T* __restrict__ Bhi, const T* __restrict__ Blo,
             float* __restrict__ C0, float* __restrict__ C1,
             int N0, int N1, int K) {
    constexpr uint32_t A_SZ = 16384;
    constexpr uint32_t A_TOT = (PASSES >= 2) ? 2 * A_SZ : A_SZ;
    constexpr uint32_t B_SZ = 8192;
    constexpr uint32_t B_TOT = (PASSES == 3) ? 2 * B_SZ : B_SZ;
    constexpr uint32_t STG = A_TOT + B_TOT;
    extern __shared__ char smem[];
    const uint32_t sb = smem_u32(smem);
    const int tid = threadIdx.x, lane = tid & 31, wid = tid >> 5;
    const int m0 = blockIdx.y * 128, n0 = blockIdx.x * 64;
    const int wm = (wid >> 1) * 32, wn = (wid & 1) * 32;

    const T* aptr[4];
    uint32_t asw[4];
#pragma unroll
    for (int i = 0; i < 4; ++i) {
        int idx = tid + (i << 8);
        int r = idx >> 3, c = idx & 7;
        aptr[i] = Ahi + (size_t)(m0 + r) * K + (c << 3);
        asw[i] = swz(r * 128 + c * 16);
    }
    const T* bptr[2];
    uint32_t bsw[2];
#pragma unroll
    for (int i = 0; i < 2; ++i) {
        int idx = tid + (i << 8);
        int r = idx >> 3, c = idx & 7;
        bptr[i] = Bhi + (size_t)(n0 + r) * K + (c << 3);
        bsw[i] = swz(r * 128 + c * 16);
    }
    const ptrdiff_t dA = (PASSES >= 2) ? (Alo - Ahi) : 0;
    const ptrdiff_t dB = (PASSES == 3) ? (Blo - Bhi) : 0;

    float acc[2][4][4];
#pragma unroll
    for (int mt = 0; mt < 2; ++mt)
#pragma unroll
        for (int nt = 0; nt < 4; ++nt)
#pragma unroll
            for (int q = 0; q < 4; ++q) acc[mt][nt][q] = 0.f;

    const int NKT = K >> 6;
#pragma unroll
    for (int s = 0; s < 2; ++s) {
        const uint32_t st = sb + s * STG;
        const int ko = s * 64;
#pragma unroll
        for (int i = 0; i < 4; ++i) {
            cp16(st + asw[i], aptr[i] + ko);
            if (PASSES >= 2) cp16(st + A_SZ + asw[i], aptr[i] + dA + ko);
        }
#pragma unroll
        for (int i = 0; i < 2; ++i) {
            cp16(st + A_TOT + bsw[i], bptr[i] + ko);
            if (PASSES == 3) cp16(st + A_TOT + B_SZ + bsw[i], bptr[i] + dB + ko);
        }
        CP_COMMIT();
    }

    const int row_off = ((lane >> 3) & 1) * 8 + (lane & 7);
    const int kxtra = (lane >> 4) * 16;
    const uint32_t a_lb = (uint32_t)((wm + row_off) * 128 + kxtra);
    const uint32_t b_lb = (uint32_t)((wn + row_off) * 128 + kxtra);

    for (int kt = 0; kt < NKT; ++kt) {
        CP_WAIT1();
        __syncthreads();
        const uint32_t st = sb + (uint32_t)(kt & 1) * STG;
#pragma unroll
        for (int ks = 0; ks < 4; ++ks) {
            uint32_t ah[2][4], al[2][4], bh[2][4];
#pragma unroll
            for (int mt = 0; mt < 2; ++mt) {
                uint32_t off = swz(a_lb + mt * 16 * 128 + ks * 32);
                ldsm_x4(ah[mt][0], ah[mt][1], ah[mt][2], ah[mt][3], st + off);
                if (PASSES >= 2)
                    ldsm_x4(al[mt][0], al[mt][1], al[mt][2], al[mt][3], st + A_SZ + off);
            }
#pragma unroll
            for (int nt2 = 0; nt2 < 2; ++nt2)
                ldsm_x4(bh[nt2][0], bh[nt2][1], bh[nt2][2], bh[nt2][3],
                        st + A_TOT + swz(b_lb + nt2 * 16 * 128 + ks * 32));
            if (PASSES == 3) {
                uint32_t bl[2][4];
#pragma unroll
                for (int nt2 = 0; nt2 < 2; ++nt2)
                    ldsm_x4(bl[nt2][0], bl[nt2][1], bl[nt2][2], bl[nt2][3],
                            st + A_TOT + B_SZ + swz(b_lb + nt2 * 16 * 128 + ks * 32));
#pragma unroll
                for (int mt = 0; mt < 2; ++mt)
#pragma unroll
                    for (int nt = 0; nt < 4; ++nt) {
                        MmaOp<T>::run(acc[mt][nt], ah[mt],
                                      bh[nt >> 1][nt & 1], bh[nt >> 1][2 + (nt & 1)]);
                        MmaOp<T>::run(acc[mt][nt], ah[mt],
                                      bl[nt >> 1][nt & 1], bl[nt >> 1][2 + (nt & 1)]);
                        MmaOp<T>::run(acc[mt][nt], al[mt],
                                      bh[nt >> 1][nt & 1], bh[nt >> 1][2 + (nt & 1)]);
                    }
            } else if (PASSES == 2) {
#pragma unroll
                for (int mt = 0; mt < 2; ++mt)
#pragma unroll
                    for (int nt = 0; nt < 4; ++nt) {
                        MmaOp<T>::run(acc[mt][nt], ah[mt],
                                      bh[nt >> 1][nt & 1], bh[nt >> 1][2 + (nt & 1)]);
                        MmaOp<T>::run(acc[mt][nt], al[mt],
                                      bh[nt >> 1][nt & 1], bh[nt >> 1][2 + (nt & 1)]);
                    }
            } else {
#pragma unroll
                for (int mt = 0; mt < 2; ++mt)
#pragma unroll
                    for (int nt = 0; nt < 4; ++nt)
                        MmaOp<T>::run(acc[mt][nt], ah[mt],
                                      bh[nt >> 1][nt & 1], bh[nt >> 1][2 + (nt & 1)]);
            }
        }
        __syncthreads();
        if (kt + 2 < NKT) {
            const uint32_t st2 = sb + (uint32_t)(kt & 1) * STG;
            const int ko = (kt + 2) * 64;
#pragma unroll
            for (int i = 0; i < 4; ++i) {
                cp16(st2 + asw[i], aptr[i] + ko);
                if (PASSES >= 2) cp16(st2 + A_SZ + asw[i], aptr[i] + dA + ko);
            }
#pragma unroll
            for (int i = 0; i < 2; ++i) {
                cp16(st2 + A_TOT + bsw[i], bptr[i] + ko);
                if (PASSES == 3) cp16(st2 + A_TOT + B_SZ + bsw[i], bptr[i] + dB + ko);
            }
        }
        CP_COMMIT();
    }

    float* Cc;
    int Nc, col0;
    if (n0 < N0) {
        Cc = C0; Nc = N0; col0 = n0;
    } else {
        Cc = C1; Nc = N1; col0 = n0 - N0;
    }
#pragma unroll
    for (int mt = 0; mt < 2; ++mt) {
        const int row = m0 + wm + mt * 16 + (lane >> 2);
#pragma unroll
        for (int nt = 0; nt < 4; ++nt) {
            const int col = col0 + wn + nt * 8 + (lane & 3) * 2;
            float* p0 = Cc + (size_t)row * Nc + col;
            *(float2*)p0 = make_float2(acc[mt][nt][0], acc[mt][nt][1]);
            *(float2*)(p0 + 8 * (size_t)Nc) = make_float2(acc[mt][nt][2], acc[mt][nt][3]);
        }
    }
}

// ---------------- RoPE ----------------
__global__ void rope_kernel(float* __restrict__ X, int nh) {
    const int s = blockIdx.x;
    const int d = threadIdx.x;
    const float e = (float)d * (1.0f / 64.0f);
    const float invf = 1.0f / powf(10000.0f, e);
    const float ang = (float)s * invf;
    float sn, cs;
    sincosf(ang, &sn, &cs);
    float* p = X + (size_t)s * nh * DH;
    for (int h = 0; h < nh; ++h) {
        const float x1 = p[d];
        const float x2 = p[d + 64];
        p[d] = x1 * cs - x2 * sn;
        p[d + 64] = x2 * cs + x1 * sn;
        p += DH;
    }
}

// ---------------- fused attention (query-pair score blocking + row-union AV) ----------------
#define QP 132
#define KP 132
__global__ __launch_bounds__(512, 1)
void fused_attn_kernel(const float* __restrict__ Q, const float* __restrict__ K,
                       const float* __restrict__ V, __half* __restrict__ atHi) {
    extern __shared__ float sm[];
    float* sq = sm;                 // 64 x 132
    float* sk = sq + 64 * QP;       // 128 x 132 (phase2: landmark K)
    float* sv = sk + 128 * KP;      // 128 x 128 (phase2: landmark V)
    float* sc = sv + 128 * 128;     // 64 x 66

    const int tid = threadIdx.x;
    const int h = blockIdx.y;
    const int n = blockIdx.x;
    const int kvh = h >> 2;
    const int q0 = n * 64;
    const int key0 = q0 - 64;
    const int w = tid >> 5, lane = tid & 31;

#pragma unroll
    for (int it = 0; it < 4; ++it) {
        int idx = tid + it * 512;
        int r = idx >> 5, c4 = idx & 31;
        float4 v4 = *(const float4*)&Q[(size_t)(q0 + r) * (NH * DH) + h * DH + c4 * 4];
        *(float4*)&sq[r * QP + c4 * 4] = v4;
    }
#pragma unroll
    for (int it = 0; it < 8; ++it) {
        int idx = tid + it * 512;
        int r = idx >> 5, c4 = idx & 31;
        int pos = key0 + r;
        float4 kv = make_float4(0.f, 0.f, 0.f, 0.f);
        float4 vv = make_float4(0.f, 0.f, 0.f, 0.f);
        if (pos >= 0) {
            kv = *(const float4*)&K[(size_t)pos * (NKV * DH) + kvh * DH + c4 * 4];
            vv = *(const float4*)&V[(size_t)pos * (NKV * DH) + kvh * DH + c4 * 4];
        }
        *(float4*)&sk[r * KP + c4 * 4] = kv;
        *(float4*)&sv[r * 128 + c4 * 4] = vv;
    }
    __syncthreads();

    // ---- phase 1 scores: query-pair blocking ----
    {
        const int i2 = tid >> 4;
        const int jo = tid & 15;
        const int qa = 2 * i2, qb = qa + 1;
        ull sa[4], sb[4];
        ull sx0 = 0, sx1 = 0, sx2 = 0;
#pragma unroll
        for (int m = 0; m < 4; ++m) sa[m] = sb[m] = 0;
        const float* qra = sq + qa * QP;
        const float* qrb = sq + qb * QP;
        for (int d0 = 0; d0 < 128; d0 += 8) {
            ull qav[4], qbv[4];
#pragma unroll
            for (int u = 0; u < 4; ++u) {
                qav[u] = *(const ull*)&qra[d0 + 2 * u];
                qbv[u] = *(const ull*)&qrb[d0 + 2 * u];
            }
#pragma unroll
            for (int m = 0; m < 4; ++m) {
                const ull* kr = (const ull*)(sk + (qa + jo + 16 * m) * KP + d0);
                ull k0 = kr[0], k1 = kr[1], k2 = kr[2], k3 = kr[3];
                sa[m] = fma2(qav[0], k0, sa[m]);
                sa[m] = fma2(qav[1], k1, sa[m]);
                sa[m] = fma2(qav[2], k2, sa[m]);
                sa[m] = fma2(qav[3], k3, sa[m]);
                sb[m] = fma2(qbv[0], k0, sb[m]);
                sb[m] = fma2(qbv[1], k1, sb[m]);
                sb[m] = fma2(qbv[2], k2, sb[m]);
                sb[m] = fma2(qbv[3], k3, sb[m]);
            }
            if (jo == 0) {
                const ull* kr = (const ull*)(sk + (qa + 64) * KP + d0);
#pragma unroll
                for (int u = 0; u < 4; ++u) {
                    sx0 = fma2(qav[u], kr[u], sx0);
                    sx1 = fma2(qbv[u], kr[u], sx1);
                }
            }
            if (jo == 1) {
                const ull* kr = (const ull*)(sk + (qa + 65) * KP + d0);
#pragma unroll
                for (int u = 0; u < 4; ++u) sx2 = fma2(qbv[u], kr[u], sx2);
            }
        }
#pragma unroll
        for (int m = 0; m < 4; ++m) {
            int jja = jo + 16 * m;
            sc[qa * 66 + jja] = lo2(sa[m]) * ATT_SCALE;
            int jjb = jja - 1;
            if (jjb >= 0) sc[qb * 66 + jjb] = lo2(sb[m]) * ATT_SCALE;
        }
        if (jo == 0) {
            sc[qa * 66 + 64] = lo2(sx0) * ATT_SCALE;
            sc[qb * 66 + 63] = lo2(sx1) * ATT_SCALE;
        }
        if (jo == 1) sc[qb * 66 + 64] = lo2(sx2) * ATT_SCALE;
    }
    __syncthreads();

    if (tid < 64) {
        float* row = sc + tid * 66;
        float mx = row[0];
        for (int j = 1; j < 65; ++j) mx = fmaxf(mx, row[j]);
        float sum = 0.f;
        for (int j = 0; j < 65; ++j) {
            float ex = expf(row[j] - mx);
            row[j] = ex;
            sum += ex;
        }
        float inv = 1.f / sum;
        for (int j = 0; j < 65; ++j) row[j] *= inv;
    }
    __syncthreads();

    // ---- phase 1 AV: row-union ----
    ull lo_[4][2];
#pragma unroll
    for (int iq = 0; iq < 4; ++iq) lo_[iq][0] = lo_[iq][1] = 0;
    {
        const int qb2 = w * 4;
        for (int rr = 0; rr < 68; ++rr) {
            const ull* v2 = (const ull*)(sv + (qb2 + rr) * 128 + lane * 4);
            ull v0 = v2[0], v1 = v2[1];
#pragma unroll
            for (int iq = 0; iq < 4; ++iq) {
                int jj = rr - iq;
                if (jj >= 0 && jj <= 64) {
                    ull wt2 = dup2(sc[(qb2 + iq) * 66 + jj]);
                    lo_[iq][0] = fma2(wt2, v0, lo_[iq][0]);
                    lo_[iq][1] = fma2(wt2, v1, lo_[iq][1]);
                }
            }
        }
    }
    __syncthreads();

    // ---- phase 2: landmark K/V ----
#pragma unroll
    for (int it = 0; it < 4; ++it) {
        int idx = tid + it * 512;
        int r = idx >> 5, c4 = idx & 31;
        int pos = r * 64;
        *(float4*)&sk[r * KP + c4 * 4] =
            *(const float4*)&K[(size_t)pos * (NKV * DH) + kvh * DH + c4 * 4];
        *(float4*)&sv[r * 128 + c4 * 4] =
            *(const float4*)&V[(size_t)pos * (NKV * DH) + kvh * DH + c4 * 4];
    }
    __syncthreads();

    const int nvis = n + 1;
    // ---- phase 2 scores: query-pair blocking + nvis bound ----
    {
        const int i2 = tid >> 4;
        const int jo = tid & 15;
        const int qa = 2 * i2, qb = qa + 1;
        ull s2[4][2];
#pragma unroll
        for (int m = 0; m < 4; ++m) s2[m][0] = s2[m][1] = 0;
        const float* qra = sq + qa * QP;
        const float* qrb = sq + qb * QP;
        for (int d0 = 0; d0 < 128; d0 += 8) {
            ull qav[4], qbv[4];
#pragma unroll
            for (int u = 0; u < 4; ++u) {
                qav[u] = *(const ull*)&qra[d0 + 2 * u];
                qbv[u] = *(const ull*)&qrb[d0 + 2 * u];
            }
#pragma unroll
            for (int m = 0; m < 4; ++m) {
                int key = jo + 16 * m;
                if (key < nvis) {
                    const ull* kr = (const ull*)(sk + key * KP + d0);
                    ull k0 = kr[0], k1 = kr[1], k2 = kr[2], k3 = kr[3];
                    s2[m][0] = fma2(qav[0], k0, s2[m][0]);
                    s2[m][0] = fma2(qav[1], k1, s2[m][0]);
                    s2[m][0] = fma2(qav[2], k2, s2[m][0]);
                    s2[m][0] = fma2(qav[3], k3, s2[m][0]);
                    s2[m][1] = fma2(qbv[0], k0, s2[m][1]);
                    s2[m][1] = fma2(qbv[1], k1, s2[m][1]);
                    s2[m][1] = fma2(qbv[2], k2, s2[m][1]);
                    s2[m][1] = fma2(qbv[3], k3, s2[m][1]);
                }
            }
        }
#pragma unroll
        for (int m = 0; m < 4; ++m) {
            int key = jo + 16 * m;
            if (key < nvis) {
                sc[qa * 66 + key] = lo2(s2[m][0]) * ATT_SCALE;
                sc[qb * 66 + key] = lo2(s2[m][1]) * ATT_SCALE;
            }
        }
    }
    __syncthreads();

    if (tid < 64) {
        float* row = sc + tid * 66;
        float mx = row[0];
        for (int j = 1; j < nvis; ++j) mx = fmaxf(mx, row[j]);
        float sum = 0.f;
        for (int j = 0; j < nvis; ++j) {
            float ex = expf(row[j] - mx);
            row[j] = ex;
            sum += ex;
        }
        float inv = 1.f / sum;
        for (int j = 0; j < nvis; ++j) row[j] *= inv;
    }
    __syncthreads();

    // ---- phase 2 AV (V row hoisted) + combine + store fp16 ----
    {
        ull go[4][2];
#pragma unroll
        for (int iq = 0; iq < 4; ++iq) go[iq][0] = go[iq][1] = 0;
        const int qb2 = w * 4;
        for (int jj = 0; jj < nvis; ++jj) {
            const ull* v2 = (const ull*)(sv + jj * 128 + lane * 4);
            ull v0 = v2[0], v1 = v2[1];
#pragma unroll
            for (int iq = 0; iq < 4; ++iq) {
                ull wt2 = dup2(sc[(qb2 + iq) * 66 + jj]);
                go[iq][0] = fma2(wt2, v0, go[iq][0]);
                go[iq][1] = fma2(wt2, v1, go[iq][1]);
            }
        }
#pragma unroll
        for (int iq = 0; iq < 4; ++iq) {
            const int i = qb2 + iq;
            float2 ga = unp2(go[iq][0]), gb = unp2(go[iq][1]);
            float2 la = unp2(lo_[iq][0]), lb = unp2(lo_[iq][1]);
            float s4[4] = {0.7f * la.x + 0.3f * ga.x, 0.7f * la.y + 0.3f * ga.y,
                           0.7f * lb.x + 0.3f * gb.x, 0.7f * lb.y + 0.3f * gb.y};
            size_t idx = (size_t)(q0 + i) * (NH * DH) + h * DH + lane * 4;
            union { __half b2[4]; uint2 u; } H;
#pragma unroll
            for (int q = 0; q < 4; ++q) H.b2[q] = __float2half_rn(s4[q]);
            *(uint2*)&atHi[idx] = H.u;
        }
    }
}

// ---------------- launch ----------------
extern "C" void kernel_launch(void* const* d_in, const int* in_sizes, int n_in,
                              void* d_out, int out_size) {
    const float* hs = (const float*)d_in[0];
    const float* wq = (const float*)d_in[1];
    const float* wk = (const float*)d_in[2];
    const float* wv = (const float*)d_in[3];
    const float* wo = (const float*)d_in[4];
    float* out = (float*)d_out;

    float *Q, *K, *V;
    __nv_bfloat16 *hsHi, *hsLo, *wqkTHi, *wqkTLo;
    __half *hs16h, *wvT16, *woT16, *at16h;
    cudaGetSymbolAddress((void**)&Q, g_Q);
    cudaGetSymbolAddress((void**)&K, g_K);
    cudaGetSymbolAddress((void**)&V, g_V);
    cudaGetSymbolAddress((void**)&hsHi, g_hsHi);
    cudaGetSymbolAddress((void**)&hsLo, g_hsLo);
    cudaGetSymbolAddress((void**)&hs16h, g_hs16h);
    cudaGetSymbolAddress((void**)&wqkTHi, g_wqkTHi);
    cudaGetSymbolAddress((void**)&wqkTLo, g_wqkTLo);
    cudaGetSymbolAddress((void**)&wvT16, g_wvT16);
    cudaGetSymbolAddress((void**)&woT16, g_woT16);
    cudaGetSymbolAddress((void**)&at16h, g_at16h);

    const int SMEM_ATT = (64 * QP + 128 * KP + 128 * 128 + 64 * 66) * 4;
    const int SMEM_G3 = 2 * (32768 + 16384);  // 98304
    const int SMEM_G1 = 2 * (16384 + 8192);   // 49152
    cudaFuncSetAttribute(fused_attn_kernel, cudaFuncAttributeMaxDynamicSharedMemorySize, SMEM_ATT);
    cudaFuncSetAttribute(gemm_tc<__nv_bfloat16, 3>,
                         cudaFuncAttributeMaxDynamicSharedMemorySize, SMEM_G3);
    cudaFuncSetAttribute(gemm_tc<__half, 1>,
                         cudaFuncAttributeMaxDynamicSharedMemorySize, SMEM_G1);

    // conversions feeding QK gemm
    split_all_kernel<<<(S_LEN * HID) / 1024, 256>>>(hs, hsHi, hsLo, hs16h);
    transpose_split_kernel<<<dim3(HID / 32, HID / 32), dim3(32, 8)>>>(
        wq, wqkTHi, wqkTLo, HID, HID);
    transpose_split_kernel<<<dim3((NKV * DH) / 32, HID / 32), dim3(32, 8)>>>(
        wk, wqkTHi + (size_t)HID * HID, wqkTLo + (size_t)HID * HID, HID, NKV * DH);

    // fused Q+K gemm (ncu capture slot 4)
    gemm_tc<__nv_bfloat16, 3><<<dim3((HID + NKV * DH) / 64, S_LEN / 128), 256, SMEM_G3>>>(
        hsHi, hsLo, wqkTHi, wqkTLo, Q, K, NH * DH, NKV * DH, HID);

    transpose_f16_kernel<<<dim3((NKV * DH) / 32, HID / 32), dim3(32, 8)>>>(wv, wvT16, HID, NKV * DH);
    // V projection: single-pass fp16
    gemm_tc<__half, 1><<<dim3((NKV * DH) / 64, S_LEN / 128), 256, SMEM_G1>>>(
        hs16h, (const __half*)nullptr, wvT16, (const __half*)nullptr, V, V, NKV * DH, 0, HID);

    transpose_f16_kernel<<<dim3(HID / 32, HID / 32), dim3(32, 8)>>>(wo, woT16, HID, HID);

    rope_kernel<<<S_LEN, 64>>>(Q, NH);
    rope_kernel<<<S_LEN, 64>>>(K, NKV);

    fused_attn_kernel<<<dim3(S_LEN / 64, NH), 512, SMEM_ATT>>>(Q, K, V, at16h);

    // O projection: single-pass fp16
    gemm_tc<__half, 1><<<dim3(HID / 64, S_LEN / 128), 256, SMEM_G1>>>(
        at16h, (const __half*)nullptr, woT16, (const __half*)nullptr, out, out, HID, 0, HID);
}